// round 3
// baseline (speedup 1.0000x reference)
#include <cuda_runtime.h>
#include <stdint.h>
#include <math.h>

// ---------------------------------------------------------------------------
// MoE: gate -> top2 route -> capacity dispatch -> 8x SwiGLU expert MLP -> combine
// Shapes: N_TOK=16384 tokens, d=1024, E=8, K(topk)=2, CAP=4096, DFF=3072 (SwiGLU->1536)
// ---------------------------------------------------------------------------

#define N_TOK   16384
#define DM      1024
#define NE      8
#define CAP     4096
#define DFF     3072
#define DH      1536          // DFF/2
#define NSLOT   (N_TOK * 2)   // 32768
#define NBLK    32            // scan blocks (NSLOT / 1024)

// ---- scratch (device globals: allocation-free rule) ----
__device__ float g_expx[(size_t)NE * CAP * DM];    // [E, CAP, d]   dispatched tokens
__device__ float g_H  [(size_t)NE * CAP * DFF];    // [E, CAP, 3d]  fc output
__device__ float g_hg [(size_t)NE * CAP * DH];     // [E, CAP, 1.5d] after SwiGLU
__device__ float g_eo [(size_t)NE * CAP * DM];     // [E, CAP, d]   expert output
__device__ int   g_se[NSLOT];                      // expert id per slot
__device__ float g_sw[NSLOT];                      // gate weight per slot
__device__ int   g_sp[NSLOT];                      // position in expert (-1 = dropped)
__device__ int   g_bcnt[NBLK * NE];
__device__ int   g_boff[NBLK * NE];

// ---------------------------------------------------------------------------
// Kernel 1: gate logits -> softmax -> top2 (ties: lowest index, = jax top_k)
// 1 warp per token, w_gate cached in smem transposed [e][d]
// ---------------------------------------------------------------------------
__global__ void gate_kernel(const float* __restrict__ x,
                            const float* __restrict__ wg) {
    __shared__ float wgs[NE][DM];   // 32 KB
    const int tid = threadIdx.x;
    for (int i = tid; i < NE * DM; i += blockDim.x) {
        // wg is [DM, NE] row-major: i = d*8 + e
        wgs[i & 7][i >> 3] = wg[i];
    }
    __syncthreads();

    const int warp = tid >> 5, lane = tid & 31;
    const int n = blockIdx.x * 4 + warp;

    float acc[NE];
    #pragma unroll
    for (int e = 0; e < NE; e++) acc[e] = 0.f;

    const float* xr = x + (size_t)n * DM;
    for (int j = lane; j < DM; j += 32) {
        const float xv = xr[j];
        #pragma unroll
        for (int e = 0; e < NE; e++) acc[e] += xv * wgs[e][j];
    }
    #pragma unroll
    for (int off = 16; off; off >>= 1) {
        #pragma unroll
        for (int e = 0; e < NE; e++)
            acc[e] += __shfl_xor_sync(0xffffffffu, acc[e], off);
    }

    if (lane == 0) {
        float m = acc[0];
        #pragma unroll
        for (int e = 1; e < NE; e++) m = fmaxf(m, acc[e]);
        float p[NE], s = 0.f;
        #pragma unroll
        for (int e = 0; e < NE; e++) { p[e] = expf(acc[e] - m); s += p[e]; }
        const float inv = 1.f / s;
        #pragma unroll
        for (int e = 0; e < NE; e++) p[e] *= inv;

        int e1 = 0;
        #pragma unroll
        for (int e = 1; e < NE; e++) if (p[e] > p[e1]) e1 = e;
        int e2 = (e1 == 0) ? 1 : 0;
        #pragma unroll
        for (int e = 0; e < NE; e++) if (e != e1 && p[e] > p[e2]) e2 = e;

        g_se[2*n]     = e1;  g_sw[2*n]     = p[e1];
        g_se[2*n + 1] = e2;  g_sw[2*n + 1] = p[e2];
    }
}

// ---------------------------------------------------------------------------
// Kernels 2a/2b/2c: per-expert exclusive rank over slots in flat order
// ---------------------------------------------------------------------------
__global__ void count_kernel() {
    __shared__ int c[NE];
    if (threadIdx.x < NE) c[threadIdx.x] = 0;
    __syncthreads();
    const int s = blockIdx.x * 1024 + threadIdx.x;
    atomicAdd(&c[g_se[s]], 1);
    __syncthreads();
    if (threadIdx.x < NE) g_bcnt[blockIdx.x * NE + threadIdx.x] = c[threadIdx.x];
}

__global__ void scan_kernel() {
    const int e = threadIdx.x;   // 8 threads
    int run = 0;
    for (int b = 0; b < NBLK; b++) {
        g_boff[b * NE + e] = run;
        run += g_bcnt[b * NE + e];
    }
}

__global__ void pos_kernel() {
    __shared__ int el[1024];
    const int t = threadIdx.x;
    const int s = blockIdx.x * 1024 + t;
    const int e = g_se[s];
    el[t] = e;
    __syncthreads();
    int r = g_boff[blockIdx.x * NE + e];
    for (int j = 0; j < t; j++) r += (el[j] == e);
    g_sp[s] = (r < CAP) ? r : -1;
}

// ---------------------------------------------------------------------------
// Kernel 3: scatter x rows into exp_x (collision-free; dropped slots skipped)
// ---------------------------------------------------------------------------
__global__ void scatter_kernel(const float* __restrict__ x) {
    const int s = blockIdx.x;
    const int p = g_sp[s];
    if (p < 0) return;
    const int e = g_se[s];
    const int tok = s >> 1;
    const float4* src = (const float4*)(x + (size_t)tok * DM);
    float4* dst = (float4*)(g_expx + ((size_t)e * CAP + p) * DM);
    dst[threadIdx.x] = src[threadIdx.x];
}

// ---------------------------------------------------------------------------
// Batched SGEMM (NN, row-major): C[z] = A[z] @ B[z]
// 128x128x16 tiles, double-buffered smem, 8x8 microtile via packed fma.rn.f32x2
// which==0: A=g_expx C=g_H ; which==1: A=g_hg C=g_eo. M=CAP fixed.
// ---------------------------------------------------------------------------
__global__ void __launch_bounds__(256, 2)
sgemm_nn(const int which, const float* __restrict__ Bg, const int N, const int K)
{
    const int M = CAP;
    const float* __restrict__ A;
    float* __restrict__ C;
    if (which == 0) { A = g_expx; C = g_H; }
    else            { A = g_hg;   C = g_eo; }

    const size_t z = blockIdx.z;
    A += z * (size_t)M * K;
    const float* __restrict__ B = Bg + z * (size_t)K * N;
    C += z * (size_t)M * N;

    __shared__ __align__(16) float sA[2][16][128];   // A^T tile: [k][m]
    __shared__ __align__(16) float sB[2][16][128];   // B tile:   [k][n]

    const int tid = threadIdx.x;
    const int bm = blockIdx.y * 128;
    const int bn = blockIdx.x * 128;

    const int ar  = tid >> 2;   // A load: row group (0..63), +64 on 2nd pass
    const int ac4 = tid & 3;    //         col float4 (0..3)
    const int br  = tid >> 5;   // B load: row (0..7), +8 on 2nd pass
    const int bc4 = tid & 31;   //         col float4 (0..31)
    const int ty  = tid >> 4;   // compute: 16x16 thread grid
    const int tx  = tid & 15;

    uint64_t acc[8][4];
    #pragma unroll
    for (int i = 0; i < 8; i++)
        #pragma unroll
        for (int j = 0; j < 4; j++) acc[i][j] = 0ull;

    const int ntiles = K >> 4;
    float4 va[2], vb[2];

    // prologue: tile 0 -> smem buf 0
    #pragma unroll
    for (int it = 0; it < 2; it++) {
        va[it] = *(const float4*)(A + (size_t)(bm + ar + it*64) * K + ac4*4);
        vb[it] = *(const float4*)(B + (size_t)(br + it*8) * N + bn + bc4*4);
    }
    #pragma unroll
    for (int it = 0; it < 2; it++) {
        const int r = ar + it*64;
        sA[0][ac4*4+0][r] = va[it].x;
        sA[0][ac4*4+1][r] = va[it].y;
        sA[0][ac4*4+2][r] = va[it].z;
        sA[0][ac4*4+3][r] = va[it].w;
        *(float4*)&sB[0][br + it*8][bc4*4] = vb[it];
    }
    __syncthreads();

    for (int t = 0; t < ntiles; t++) {
        const int buf = t & 1;
        if (t + 1 < ntiles) {   // prefetch next gmem tile into regs
            const int k0 = (t + 1) << 4;
            #pragma unroll
            for (int it = 0; it < 2; it++) {
                va[it] = *(const float4*)(A + (size_t)(bm + ar + it*64) * K + k0 + ac4*4);
                vb[it] = *(const float4*)(B + (size_t)(k0 + br + it*8) * N + bn + bc4*4);
            }
        }
        #pragma unroll
        for (int k = 0; k < 16; k++) {
            const float4 a0 = *(const float4*)&sA[buf][k][ty*8];
            const float4 a1 = *(const float4*)&sA[buf][k][ty*8 + 4];
            const ulonglong2 p0 = *(const ulonglong2*)&sB[buf][k][tx*8];
            const ulonglong2 p1 = *(const ulonglong2*)&sB[buf][k][tx*8 + 4];
            const uint64_t bb0 = p0.x, bb1 = p0.y, bb2 = p1.x, bb3 = p1.y;
            const float as[8] = {a0.x, a0.y, a0.z, a0.w, a1.x, a1.y, a1.z, a1.w};
            #pragma unroll
            for (int i = 0; i < 8; i++) {
                uint64_t aa;
                asm("mov.b64 %0, {%1, %1};" : "=l"(aa) : "f"(as[i]));
                asm("fma.rn.f32x2 %0, %1, %2, %0;" : "+l"(acc[i][0]) : "l"(aa), "l"(bb0));
                asm("fma.rn.f32x2 %0, %1, %2, %0;" : "+l"(acc[i][1]) : "l"(aa), "l"(bb1));
                asm("fma.rn.f32x2 %0, %1, %2, %0;" : "+l"(acc[i][2]) : "l"(aa), "l"(bb2));
                asm("fma.rn.f32x2 %0, %1, %2, %0;" : "+l"(acc[i][3]) : "l"(aa), "l"(bb3));
            }
        }
        if (t + 1 < ntiles) {
            const int nb = buf ^ 1;
            #pragma unroll
            for (int it = 0; it < 2; it++) {
                const int r = ar + it*64;
                sA[nb][ac4*4+0][r] = va[it].x;
                sA[nb][ac4*4+1][r] = va[it].y;
                sA[nb][ac4*4+2][r] = va[it].z;
                sA[nb][ac4*4+3][r] = va[it].w;
                *(float4*)&sB[nb][br + it*8][bc4*4] = vb[it];
            }
            __syncthreads();
        }
    }

    // epilogue
    #pragma unroll
    for (int i = 0; i < 8; i++) {
        float o[8];
        #pragma unroll
        for (int j = 0; j < 4; j++)
            asm("mov.b64 {%0, %1}, %2;" : "=f"(o[2*j]), "=f"(o[2*j+1]) : "l"(acc[i][j]));
        float* cp = C + (size_t)(bm + ty*8 + i) * N + bn + tx*8;
        *(float4*)cp       = make_float4(o[0], o[1], o[2], o[3]);
        *(float4*)(cp + 4) = make_float4(o[4], o[5], o[6], o[7]);
    }
}

// ---------------------------------------------------------------------------
// Kernel 5: SwiGLU  h = silu(H[:, :1536]) * H[:, 1536:]
// one block per (e,c) row, 384 threads, float4 each
// ---------------------------------------------------------------------------
__global__ void swiglu_kernel() {
    const size_t row = blockIdx.x;                 // 0 .. NE*CAP-1
    const int c = threadIdx.x * 4;                 // 0 .. 1532
    const float4 a = *(const float4*)&g_H[row * DFF + c];
    const float4 g = *(const float4*)&g_H[row * DFF + DH + c];
    float4 o;
    o.x = (a.x / (1.f + expf(-a.x))) * g.x;
    o.y = (a.y / (1.f + expf(-a.y))) * g.y;
    o.z = (a.z / (1.f + expf(-a.z))) * g.z;
    o.w = (a.w / (1.f + expf(-a.w))) * g.w;
    *(float4*)&g_hg[row * DH + c] = o;
}

// ---------------------------------------------------------------------------
// Kernel 6: combine  out[n] = w0*eo[e0,p0] + w1*eo[e1,p1]  (dropped -> w=0)
// ---------------------------------------------------------------------------
__global__ void combine_kernel(float* __restrict__ out) {
    const int n = blockIdx.x;
    const int s0 = 2 * n;
    float w0 = g_sw[s0], w1 = g_sw[s0 + 1];
    int   p0 = g_sp[s0], p1 = g_sp[s0 + 1];
    const int e0 = g_se[s0], e1 = g_se[s0 + 1];
    if (p0 < 0) { w0 = 0.f; p0 = 0; }
    if (p1 < 0) { w1 = 0.f; p1 = 0; }
    const float4* r0 = (const float4*)(g_eo + ((size_t)e0 * CAP + p0) * DM);
    const float4* r1 = (const float4*)(g_eo + ((size_t)e1 * CAP + p1) * DM);
    const float4 a = r0[threadIdx.x];
    const float4 b = r1[threadIdx.x];
    float4 o;
    o.x = w0 * a.x + w1 * b.x;
    o.y = w0 * a.y + w1 * b.y;
    o.z = w0 * a.z + w1 * b.z;
    o.w = w0 * a.w + w1 * b.w;
    ((float4*)(out + (size_t)n * DM))[threadIdx.x] = o;
}

// ---------------------------------------------------------------------------
extern "C" void kernel_launch(void* const* d_in, const int* in_sizes, int n_in,
                              void* d_out, int out_size) {
    const float *x = nullptr, *wg = nullptr, *cfc = nullptr, *cpr = nullptr;
    for (int i = 0; i < n_in; i++) {
        switch (in_sizes[i]) {
            case 16777216: x   = (const float*)d_in[i]; break;  // [8,2048,1024]
            case 8192:     wg  = (const float*)d_in[i]; break;  // [1024,8]
            case 25165824: cfc = (const float*)d_in[i]; break;  // [8,1024,3072]
            case 12582912: cpr = (const float*)d_in[i]; break;  // [8,1536,1024]
        }
    }
    float* out = (float*)d_out;

    gate_kernel  <<<N_TOK / 4, 128>>>(x, wg);
    count_kernel <<<NBLK, 1024>>>();
    scan_kernel  <<<1, NE>>>();
    pos_kernel   <<<NBLK, 1024>>>();
    scatter_kernel<<<NSLOT, 256>>>(x);

    sgemm_nn<<<dim3(DFF / 128, CAP / 128, NE), 256>>>(0, cfc, DFF, DM);   // [4096,1024]@[1024,3072]
    swiglu_kernel<<<NE * CAP, DH / 4>>>();
    sgemm_nn<<<dim3(DM / 128, CAP / 128, NE), 256>>>(1, cpr, DM, DH);     // [4096,1536]@[1536,1024]

    combine_kernel<<<N_TOK, 256>>>(out);
}

// round 5
// speedup vs baseline: 1.9786x; 1.9786x over previous
#include <cuda_runtime.h>
#include <cuda_bf16.h>
#include <stdint.h>
#include <math.h>

// ---------------------------------------------------------------------------
// MoE: gate -> top2 route -> capacity dispatch -> 8x SwiGLU expert MLP -> combine
// Expert GEMMs: legacy tensor-core mma.sync bf16 (3-term split Ah*Bh+Ah*Bl+Al*Bh)
// (tcgen05 unavailable: harness PTX virtual target is compute_100, not _100a)
// ---------------------------------------------------------------------------

#define N_TOK   16384
#define DM      1024
#define NE      8
#define CAP     4096
#define DFF     3072
#define DH      1536
#define NSLOT   (N_TOK * 2)
#define NBLK    32

// GEMM tiling
#define TM      128
#define TN      256
#define TK      32
#define STAGES  3
#define SPAD    40                     // padded row: 32 bf16 + 8 pad = 80 bytes
#define STAGE_B (4 * 128 * 80 + 2 * 128 * 80)  // Ah,Al (128 rows) + Bh,Bl (256 rows) = 61440
#define GEMM_SMEM (STAGES * 61440)

// ---- scratch (device globals: allocation-free rule) ----
__device__ float g_H [(size_t)NE * CAP * DFF];     // fc output (fp32)
__device__ float g_eo[(size_t)NE * CAP * DM];      // expert output (fp32)
__device__ __nv_bfloat16 g_axh[(size_t)NE * CAP * DM];   // dispatched x, hi
__device__ __nv_bfloat16 g_axl[(size_t)NE * CAP * DM];   // dispatched x, lo
__device__ __nv_bfloat16 g_hgh[(size_t)NE * CAP * DH];   // swiglu out, hi
__device__ __nv_bfloat16 g_hgl[(size_t)NE * CAP * DH];   // swiglu out, lo
__device__ __nv_bfloat16 g_w1h[(size_t)NE * DFF * DM];   // W1^T [E][3072][1024] hi
__device__ __nv_bfloat16 g_w1l[(size_t)NE * DFF * DM];
__device__ __nv_bfloat16 g_w2h[(size_t)NE * DM * DH];    // W2^T [E][1024][1536] hi
__device__ __nv_bfloat16 g_w2l[(size_t)NE * DM * DH];
__device__ int   g_se[NSLOT];
__device__ float g_sw[NSLOT];
__device__ int   g_sp[NSLOT];
__device__ int   g_bcnt[NBLK * NE];
__device__ int   g_boff[NBLK * NE];

// ---------------------------------------------------------------------------
// helpers
// ---------------------------------------------------------------------------
__device__ __forceinline__ uint32_t smem_u32(const void* p) {
    uint32_t a;
    asm("{ .reg .u64 t; cvta.to.shared.u64 t, %1; cvt.u32.u64 %0, t; }"
        : "=r"(a) : "l"(p));
    return a;
}
__device__ __forceinline__ void cp16(uint32_t dst, const void* src) {
    asm volatile("cp.async.cg.shared.global [%0], [%1], 16;" :: "r"(dst), "l"(src));
}
#define CP_COMMIT() asm volatile("cp.async.commit_group;" ::: "memory")

#define LDSM4(v, addr) \
    asm volatile("ldmatrix.sync.aligned.m8n8.x4.shared.b16 {%0,%1,%2,%3}, [%4];" \
        : "=r"((v)[0]), "=r"((v)[1]), "=r"((v)[2]), "=r"((v)[3]) : "r"(addr))

#define MMA16816(c, a, b0, b1) \
    asm volatile("mma.sync.aligned.m16n8k16.row.col.f32.bf16.bf16.f32 " \
        "{%0,%1,%2,%3}, {%4,%5,%6,%7}, {%8,%9}, {%0,%1,%2,%3};" \
        : "+f"((c)[0]), "+f"((c)[1]), "+f"((c)[2]), "+f"((c)[3]) \
        : "r"((a)[0]), "r"((a)[1]), "r"((a)[2]), "r"((a)[3]), "r"(b0), "r"(b1))

__device__ __forceinline__ void split4(float4 v, __nv_bfloat16* ph, __nv_bfloat16* pl) {
    __nv_bfloat16 h[4], l[4];
    float f[4] = {v.x, v.y, v.z, v.w};
    #pragma unroll
    for (int i = 0; i < 4; i++) {
        h[i] = __float2bfloat16(f[i]);
        l[i] = __float2bfloat16(f[i] - __bfloat162float(h[i]));
    }
    *(uint2*)ph = *(uint2*)h;
    *(uint2*)pl = *(uint2*)l;
}

// ---------------------------------------------------------------------------
// Gate: logits -> softmax -> top2 (ties: lowest index)
// ---------------------------------------------------------------------------
__global__ void gate_kernel(const float* __restrict__ x, const float* __restrict__ wg) {
    __shared__ float wgs[NE][DM];
    const int tid = threadIdx.x;
    for (int i = tid; i < NE * DM; i += blockDim.x)
        wgs[i & 7][i >> 3] = wg[i];
    __syncthreads();

    const int warp = tid >> 5, lane = tid & 31;
    const int n = blockIdx.x * 4 + warp;

    float acc[NE];
    #pragma unroll
    for (int e = 0; e < NE; e++) acc[e] = 0.f;
    const float* xr = x + (size_t)n * DM;
    for (int j = lane; j < DM; j += 32) {
        const float xv = xr[j];
        #pragma unroll
        for (int e = 0; e < NE; e++) acc[e] += xv * wgs[e][j];
    }
    #pragma unroll
    for (int off = 16; off; off >>= 1)
        #pragma unroll
        for (int e = 0; e < NE; e++)
            acc[e] += __shfl_xor_sync(0xffffffffu, acc[e], off);

    if (lane == 0) {
        float m = acc[0];
        #pragma unroll
        for (int e = 1; e < NE; e++) m = fmaxf(m, acc[e]);
        float p[NE], s = 0.f;
        #pragma unroll
        for (int e = 0; e < NE; e++) { p[e] = expf(acc[e] - m); s += p[e]; }
        const float inv = 1.f / s;
        #pragma unroll
        for (int e = 0; e < NE; e++) p[e] *= inv;
        int e1 = 0;
        #pragma unroll
        for (int e = 1; e < NE; e++) if (p[e] > p[e1]) e1 = e;
        int e2 = (e1 == 0) ? 1 : 0;
        #pragma unroll
        for (int e = 0; e < NE; e++) if (e != e1 && p[e] > p[e2]) e2 = e;
        g_se[2*n]   = e1;  g_sw[2*n]   = p[e1];
        g_se[2*n+1] = e2;  g_sw[2*n+1] = p[e2];
    }
}

// ---------------------------------------------------------------------------
// Rank: per-expert exclusive position over slots in flat order
// ---------------------------------------------------------------------------
__global__ void count_kernel() {
    __shared__ int c[NE];
    if (threadIdx.x < NE) c[threadIdx.x] = 0;
    __syncthreads();
    atomicAdd(&c[g_se[blockIdx.x * 1024 + threadIdx.x]], 1);
    __syncthreads();
    if (threadIdx.x < NE) g_bcnt[blockIdx.x * NE + threadIdx.x] = c[threadIdx.x];
}
__global__ void scan_kernel() {
    const int e = threadIdx.x;
    int run = 0;
    for (int b = 0; b < NBLK; b++) { g_boff[b * NE + e] = run; run += g_bcnt[b * NE + e]; }
}
__global__ void pos_kernel() {
    __shared__ int el[1024];
    const int t = threadIdx.x;
    const int s = blockIdx.x * 1024 + t;
    const int e = g_se[s];
    el[t] = e;
    __syncthreads();
    int r = g_boff[blockIdx.x * NE + e];
    for (int j = 0; j < t; j++) r += (el[j] == e);
    g_sp[s] = (r < CAP) ? r : -1;
}

// ---------------------------------------------------------------------------
// Scatter + bf16 hi/lo split of activations
// ---------------------------------------------------------------------------
__global__ void scatter_split(const float* __restrict__ x) {
    const int s = blockIdx.x;
    const int p = g_sp[s];
    if (p < 0) return;
    const int e = g_se[s];
    const int tok = s >> 1;
    const float4 v = ((const float4*)(x + (size_t)tok * DM))[threadIdx.x];
    const size_t o = ((size_t)e * CAP + p) * DM + threadIdx.x * 4;
    split4(v, &g_axh[o], &g_axl[o]);
}

// ---------------------------------------------------------------------------
// Weight transpose + split: W[e][K][N] -> Wt hi/lo [e][N][K]
// ---------------------------------------------------------------------------
__global__ void wsplit_kernel(const float* __restrict__ W, const int which,
                              const int K, const int N) {
    __shared__ float s[32][33];
    __nv_bfloat16* Dh = which ? g_w2h : g_w1h;
    __nv_bfloat16* Dl = which ? g_w2l : g_w1l;
    const int e = blockIdx.z;
    const int n0 = blockIdx.x * 32, k0 = blockIdx.y * 32;
    const float* src = W + (size_t)e * K * N;
    const int tx = threadIdx.x, ty = threadIdx.y;   // 32 x 8
    #pragma unroll
    for (int i = 0; i < 4; i++)
        s[ty + i*8][tx] = src[(size_t)(k0 + ty + i*8) * N + n0 + tx];
    __syncthreads();
    const size_t dbase = (size_t)e * N * K;
    #pragma unroll
    for (int i = 0; i < 4; i++) {
        const float v = s[tx][ty + i*8];
        const __nv_bfloat16 h = __float2bfloat16(v);
        const __nv_bfloat16 l = __float2bfloat16(v - __bfloat162float(h));
        const size_t o = dbase + (size_t)(n0 + ty + i*8) * K + k0 + tx;
        Dh[o] = h;  Dl[o] = l;
    }
}

// ---------------------------------------------------------------------------
// Batched GEMM: C[e][M][N] = A[e][M][K] @ B[e][N][K]^T  (3-term bf16 split)
// CTA 128x256xK, 512 threads, 3-stage cp.async pipeline, warp tile 64x32.
// ---------------------------------------------------------------------------
__device__ __forceinline__ void load_stage(
    uint32_t sdst,
    const __nv_bfloat16* __restrict__ Ah, const __nv_bfloat16* __restrict__ Al,
    const __nv_bfloat16* __restrict__ Bh, const __nv_bfloat16* __restrict__ Bl,
    const int K, const int k0, const int tid)
{
    #pragma unroll
    for (int i = 0; i < 6; i++) {
        const int L = i * 512 + tid;          // 0..3071
        const int rid = L >> 2, q = L & 3;
        const __nv_bfloat16* src;
        uint32_t dst;
        if (rid < 128)      { src = Ah + (size_t)rid * K;          dst = sdst +         rid * 80; }
        else if (rid < 256) { const int r = rid - 128; src = Al + (size_t)r * K; dst = sdst + 10240 + r * 80; }
        else if (rid < 512) { const int r = rid - 256; src = Bh + (size_t)r * K; dst = sdst + 20480 + r * 80; }
        else                { const int r = rid - 512; src = Bl + (size_t)r * K; dst = sdst + 40960 + r * 80; }
        cp16(dst + q * 16, src + k0 + q * 8);
    }
}

__global__ void __launch_bounds__(512, 1)
gemm_mma(const int which, const int N, const int K)
{
    extern __shared__ char smem[];
    const uint32_t sb = smem_u32(smem);
    const int tid = threadIdx.x, wid = tid >> 5, lane = tid & 31;
    const int wm = wid & 1, wn = wid >> 1;          // 2 x 8 warp grid
    const int e = blockIdx.z, bm = blockIdx.y * TM, bn = blockIdx.x * TN;

    const __nv_bfloat16 *gAh, *gAl, *gBh, *gBl;
    float* gC;
    if (which == 0) { gAh = g_axh; gAl = g_axl; gBh = g_w1h; gBl = g_w1l; gC = g_H; }
    else            { gAh = g_hgh; gAl = g_hgl; gBh = g_w2h; gBl = g_w2l; gC = g_eo; }

    const __nv_bfloat16* Ah = gAh + ((size_t)e * CAP + bm) * K;
    const __nv_bfloat16* Al = gAl + ((size_t)e * CAP + bm) * K;
    const __nv_bfloat16* Bh = gBh + ((size_t)e * N + bn) * K;
    const __nv_bfloat16* Bl = gBl + ((size_t)e * N + bn) * K;
    float* C = gC + (size_t)e * CAP * N;

    float acc[64];
    #pragma unroll
    for (int i = 0; i < 64; i++) acc[i] = 0.f;

    const int T = K / TK;
    load_stage(sb,         Ah, Al, Bh, Bl, K, 0,  tid);  CP_COMMIT();
    load_stage(sb + 61440, Ah, Al, Bh, Bl, K, TK, tid);  CP_COMMIT();

    const int lmr = lane & 15;                // ldmatrix row within 16
    const int lmk = (lane >> 4) << 3;         // ldmatrix k offset (elems)

    for (int t = 0; t < T; t++) {
        if (t + 2 < T) {
            load_stage(sb + ((t + 2) % 3) * 61440, Ah, Al, Bh, Bl, K, (t + 2) * TK, tid);
            CP_COMMIT();
            asm volatile("cp.async.wait_group 2;" ::: "memory");
        } else if (t + 1 < T) {
            asm volatile("cp.async.wait_group 1;" ::: "memory");
        } else {
            asm volatile("cp.async.wait_group 0;" ::: "memory");
        }
        __syncthreads();

        const uint32_t sst = sb + (t % 3) * 61440;
        #pragma unroll
        for (int kk = 0; kk < 2; kk++) {
            const uint32_t koff = (kk * 16 + lmk) * 2;
            const uint32_t aA = sst + (wm * 64 + lmr) * 80 + koff;            // A hi
            const uint32_t aB = sst + 20480 + (wn * 32 + lmr) * 80 + koff;    // B hi

            uint32_t ah[16], bh[8], bt[8], q[4];
            // A hi (4 m-tiles)
            LDSM4(&ah[0],  aA);
            LDSM4(&ah[4],  aA + 1280);
            LDSM4(&ah[8],  aA + 2560);
            LDSM4(&ah[12], aA + 3840);
            // B hi (4 n-tiles via 2 x4 loads); n-tile j frag = {bh[2j], bh[2j+1]}
            LDSM4(q, aB);
            bh[0] = q[0]; bh[1] = q[2]; bh[2] = q[1]; bh[3] = q[3];
            LDSM4(q, aB + 1280);
            bh[4] = q[0]; bh[5] = q[2]; bh[6] = q[1]; bh[7] = q[3];

            #pragma unroll
            for (int i = 0; i < 4; i++)
                #pragma unroll
                for (int j = 0; j < 4; j++)
                    MMA16816(&acc[(i*4+j)*4], &ah[i*4], bh[2*j], bh[2*j+1]);

            // B lo -> Ah x Bl
            LDSM4(q, aB + 20480);
            bt[0] = q[0]; bt[1] = q[2]; bt[2] = q[1]; bt[3] = q[3];
            LDSM4(q, aB + 20480 + 1280);
            bt[4] = q[0]; bt[5] = q[2]; bt[6] = q[1]; bt[7] = q[3];
            #pragma unroll
            for (int i = 0; i < 4; i++)
                #pragma unroll
                for (int j = 0; j < 4; j++)
                    MMA16816(&acc[(i*4+j)*4], &ah[i*4], bt[2*j], bt[2*j+1]);

            // A lo (overwrite ah) -> Al x Bh
            LDSM4(&ah[0],  aA + 10240);
            LDSM4(&ah[4],  aA + 10240 + 1280);
            LDSM4(&ah[8],  aA + 10240 + 2560);
            LDSM4(&ah[12], aA + 10240 + 3840);
            #pragma unroll
            for (int i = 0; i < 4; i++)
                #pragma unroll
                for (int j = 0; j < 4; j++)
                    MMA16816(&acc[(i*4+j)*4], &ah[i*4], bh[2*j], bh[2*j+1]);
        }
        __syncthreads();
    }

    // Epilogue: direct fp32 stores (float2 pairs, +8 rows for c2/c3)
    const int g = lane >> 2, tg = lane & 3;
    #pragma unroll
    for (int i = 0; i < 4; i++) {
        const int row = bm + wm * 64 + i * 16 + g;
        #pragma unroll
        for (int j = 0; j < 4; j++) {
            const int col = bn + wn * 32 + j * 8 + tg * 2;
            float* p = C + (size_t)row * N + col;
            const float* c = &acc[(i*4+j)*4];
            *(float2*)p           = make_float2(c[0], c[1]);
            *(float2*)(p + 8 * N) = make_float2(c[2], c[3]);
        }
    }
}

// ---------------------------------------------------------------------------
// SwiGLU + bf16 hi/lo split:  hg = silu(H[:, :1536]) * H[:, 1536:]
// ---------------------------------------------------------------------------
__global__ void swiglu_split() {
    const size_t row = blockIdx.x;
    const int c = threadIdx.x * 4;
    const float4 a = *(const float4*)&g_H[row * DFF + c];
    const float4 g = *(const float4*)&g_H[row * DFF + DH + c];
    float4 o;
    o.x = (a.x / (1.f + expf(-a.x))) * g.x;
    o.y = (a.y / (1.f + expf(-a.y))) * g.y;
    o.z = (a.z / (1.f + expf(-a.z))) * g.z;
    o.w = (a.w / (1.f + expf(-a.w))) * g.w;
    split4(o, &g_hgh[row * DH + c], &g_hgl[row * DH + c]);
}

// ---------------------------------------------------------------------------
// Combine: out[n] = w0*eo[e0,p0] + w1*eo[e1,p1]
// ---------------------------------------------------------------------------
__global__ void combine_kernel(float* __restrict__ out) {
    const int n = blockIdx.x;
    const int s0 = 2 * n;
    float w0 = g_sw[s0], w1 = g_sw[s0 + 1];
    int   p0 = g_sp[s0], p1 = g_sp[s0 + 1];
    const int e0 = g_se[s0], e1 = g_se[s0 + 1];
    if (p0 < 0) { w0 = 0.f; p0 = 0; }
    if (p1 < 0) { w1 = 0.f; p1 = 0; }
    const float4 a = ((const float4*)(g_eo + ((size_t)e0 * CAP + p0) * DM))[threadIdx.x];
    const float4 b = ((const float4*)(g_eo + ((size_t)e1 * CAP + p1) * DM))[threadIdx.x];
    float4 o;
    o.x = w0 * a.x + w1 * b.x;
    o.y = w0 * a.y + w1 * b.y;
    o.z = w0 * a.z + w1 * b.z;
    o.w = w0 * a.w + w1 * b.w;
    ((float4*)(out + (size_t)n * DM))[threadIdx.x] = o;
}

// ---------------------------------------------------------------------------
extern "C" void kernel_launch(void* const* d_in, const int* in_sizes, int n_in,
                              void* d_out, int out_size) {
    const float *x = nullptr, *wg = nullptr, *cfc = nullptr, *cpr = nullptr;
    for (int i = 0; i < n_in; i++) {
        switch (in_sizes[i]) {
            case 16777216: x   = (const float*)d_in[i]; break;  // [8,2048,1024]
            case 8192:     wg  = (const float*)d_in[i]; break;  // [1024,8]
            case 25165824: cfc = (const float*)d_in[i]; break;  // [8,1024,3072]
            case 12582912: cpr = (const float*)d_in[i]; break;  // [8,1536,1024]
        }
    }
    float* out = (float*)d_out;

    cudaFuncSetAttribute(gemm_mma, cudaFuncAttributeMaxDynamicSharedMemorySize, GEMM_SMEM);

    gate_kernel  <<<N_TOK / 4, 128>>>(x, wg);
    count_kernel <<<NBLK, 1024>>>();
    scan_kernel  <<<1, NE>>>();
    pos_kernel   <<<NBLK, 1024>>>();
    scatter_split<<<NSLOT, 256>>>(x);

    wsplit_kernel<<<dim3(DFF / 32, DM / 32, NE), dim3(32, 8)>>>(cfc, 0, DM, DFF);  // W1
    wsplit_kernel<<<dim3(DM / 32, DH / 32, NE), dim3(32, 8)>>>(cpr, 1, DH, DM);    // W2

    gemm_mma<<<dim3(DFF / TN, CAP / TM, NE), 512, GEMM_SMEM>>>(0, DFF, DM);   // H = X @ W1^T
    swiglu_split<<<NE * CAP, DH / 4>>>();
    gemm_mma<<<dim3(DM / TN, CAP / TM, NE), 512, GEMM_SMEM>>>(1, DM, DH);     // O = HG @ W2^T

    combine_kernel<<<N_TOK, 256>>>(out);
}

// round 6
// speedup vs baseline: 2.0534x; 1.0378x over previous
#include <cuda_runtime.h>
#include <cuda_bf16.h>
#include <stdint.h>
#include <math.h>

// ---------------------------------------------------------------------------
// MoE: gate -> top2 route -> capacity dispatch -> 8x SwiGLU expert MLP -> combine
// Expert GEMMs: mma.sync bf16, 3-term split (Ah*Bh + Ah*Bl + Al*Bh), fp32 acc.
// R6: 256 threads / 255-reg budget (kill spills), warp tile 64x64, 1 sync/iter.
// ---------------------------------------------------------------------------

#define N_TOK   16384
#define DM      1024
#define NE      8
#define CAP     4096
#define DFF     3072
#define DH      1536
#define NSLOT   (N_TOK * 2)
#define NBLK    32

// GEMM tiling
#define TM      128
#define TN      256
#define TK      32
#define STAGE_B 61440          // Ah,Al: 128*80*2  +  Bh,Bl: 256*80*2
#define GEMM_SMEM (3 * STAGE_B)

// ---- scratch (device globals: allocation-free rule) ----
__device__ float g_H [(size_t)NE * CAP * DFF];
__device__ float g_eo[(size_t)NE * CAP * DM];
__device__ __nv_bfloat16 g_axh[(size_t)NE * CAP * DM];
__device__ __nv_bfloat16 g_axl[(size_t)NE * CAP * DM];
__device__ __nv_bfloat16 g_hgh[(size_t)NE * CAP * DH];
__device__ __nv_bfloat16 g_hgl[(size_t)NE * CAP * DH];
__device__ __nv_bfloat16 g_w1h[(size_t)NE * DFF * DM];
__device__ __nv_bfloat16 g_w1l[(size_t)NE * DFF * DM];
__device__ __nv_bfloat16 g_w2h[(size_t)NE * DM * DH];
__device__ __nv_bfloat16 g_w2l[(size_t)NE * DM * DH];
__device__ int   g_se[NSLOT];
__device__ float g_sw[NSLOT];
__device__ int   g_sp[NSLOT];
__device__ int   g_bcnt[NBLK * NE];
__device__ int   g_boff[NBLK * NE];

// ---------------------------------------------------------------------------
// helpers
// ---------------------------------------------------------------------------
__device__ __forceinline__ uint32_t smem_u32(const void* p) {
    uint32_t a;
    asm("{ .reg .u64 t; cvta.to.shared.u64 t, %1; cvt.u32.u64 %0, t; }"
        : "=r"(a) : "l"(p));
    return a;
}
__device__ __forceinline__ void cp16(uint32_t dst, const void* src) {
    asm volatile("cp.async.cg.shared.global [%0], [%1], 16;" :: "r"(dst), "l"(src));
}
#define CP_COMMIT() asm volatile("cp.async.commit_group;" ::: "memory")

#define LDSM4(v, addr) \
    asm volatile("ldmatrix.sync.aligned.m8n8.x4.shared.b16 {%0,%1,%2,%3}, [%4];" \
        : "=r"((v)[0]), "=r"((v)[1]), "=r"((v)[2]), "=r"((v)[3]) : "r"(addr))

#define MMA16816(c, a, b0, b1) \
    asm volatile("mma.sync.aligned.m16n8k16.row.col.f32.bf16.bf16.f32 " \
        "{%0,%1,%2,%3}, {%4,%5,%6,%7}, {%8,%9}, {%0,%1,%2,%3};" \
        : "+f"((c)[0]), "+f"((c)[1]), "+f"((c)[2]), "+f"((c)[3]) \
        : "r"((a)[0]), "r"((a)[1]), "r"((a)[2]), "r"((a)[3]), "r"(b0), "r"(b1))

__device__ __forceinline__ void split4(float4 v, __nv_bfloat16* ph, __nv_bfloat16* pl) {
    __nv_bfloat16 h[4], l[4];
    float f[4] = {v.x, v.y, v.z, v.w};
    #pragma unroll
    for (int i = 0; i < 4; i++) {
        h[i] = __float2bfloat16(f[i]);
        l[i] = __float2bfloat16(f[i] - __bfloat162float(h[i]));
    }
    *(uint2*)ph = *(uint2*)h;
    *(uint2*)pl = *(uint2*)l;
}

// ---------------------------------------------------------------------------
// Gate: logits -> softmax -> top2 (ties: lowest index)
// ---------------------------------------------------------------------------
__global__ void gate_kernel(const float* __restrict__ x, const float* __restrict__ wg) {
    __shared__ float wgs[NE][DM];
    const int tid = threadIdx.x;
    for (int i = tid; i < NE * DM; i += blockDim.x)
        wgs[i & 7][i >> 3] = wg[i];
    __syncthreads();

    const int warp = tid >> 5, lane = tid & 31;
    const int n = blockIdx.x * 4 + warp;

    float acc[NE];
    #pragma unroll
    for (int e = 0; e < NE; e++) acc[e] = 0.f;
    const float* xr = x + (size_t)n * DM;
    for (int j = lane; j < DM; j += 32) {
        const float xv = xr[j];
        #pragma unroll
        for (int e = 0; e < NE; e++) acc[e] += xv * wgs[e][j];
    }
    #pragma unroll
    for (int off = 16; off; off >>= 1)
        #pragma unroll
        for (int e = 0; e < NE; e++)
            acc[e] += __shfl_xor_sync(0xffffffffu, acc[e], off);

    if (lane == 0) {
        float m = acc[0];
        #pragma unroll
        for (int e = 1; e < NE; e++) m = fmaxf(m, acc[e]);
        float p[NE], s = 0.f;
        #pragma unroll
        for (int e = 0; e < NE; e++) { p[e] = expf(acc[e] - m); s += p[e]; }
        const float inv = 1.f / s;
        #pragma unroll
        for (int e = 0; e < NE; e++) p[e] *= inv;
        int e1 = 0;
        #pragma unroll
        for (int e = 1; e < NE; e++) if (p[e] > p[e1]) e1 = e;
        int e2 = (e1 == 0) ? 1 : 0;
        #pragma unroll
        for (int e = 0; e < NE; e++) if (e != e1 && p[e] > p[e2]) e2 = e;
        g_se[2*n]   = e1;  g_sw[2*n]   = p[e1];
        g_se[2*n+1] = e2;  g_sw[2*n+1] = p[e2];
    }
}

// ---------------------------------------------------------------------------
// Rank: per-expert exclusive position over slots in flat order
// ---------------------------------------------------------------------------
__global__ void count_kernel() {
    __shared__ int c[NE];
    if (threadIdx.x < NE) c[threadIdx.x] = 0;
    __syncthreads();
    atomicAdd(&c[g_se[blockIdx.x * 1024 + threadIdx.x]], 1);
    __syncthreads();
    if (threadIdx.x < NE) g_bcnt[blockIdx.x * NE + threadIdx.x] = c[threadIdx.x];
}
__global__ void scan_kernel() {
    const int e = threadIdx.x;
    int run = 0;
    for (int b = 0; b < NBLK; b++) { g_boff[b * NE + e] = run; run += g_bcnt[b * NE + e]; }
}
__global__ void pos_kernel() {
    __shared__ int el[1024];
    const int t = threadIdx.x;
    const int s = blockIdx.x * 1024 + t;
    const int e = g_se[s];
    el[t] = e;
    __syncthreads();
    int r = g_boff[blockIdx.x * NE + e];
    for (int j = 0; j < t; j++) r += (el[j] == e);
    g_sp[s] = (r < CAP) ? r : -1;
}

// ---------------------------------------------------------------------------
// Scatter + bf16 hi/lo split of activations
// ---------------------------------------------------------------------------
__global__ void scatter_split(const float* __restrict__ x) {
    const int s = blockIdx.x;
    const int p = g_sp[s];
    if (p < 0) return;
    const int e = g_se[s];
    const int tok = s >> 1;
    const float4 v = ((const float4*)(x + (size_t)tok * DM))[threadIdx.x];
    const size_t o = ((size_t)e * CAP + p) * DM + threadIdx.x * 4;
    split4(v, &g_axh[o], &g_axl[o]);
}

// ---------------------------------------------------------------------------
// Weight transpose + split: W[e][K][N] -> Wt hi/lo [e][N][K]
// ---------------------------------------------------------------------------
__global__ void wsplit_kernel(const float* __restrict__ W, const int which,
                              const int K, const int N) {
    __shared__ float s[32][33];
    __nv_bfloat16* Dh = which ? g_w2h : g_w1h;
    __nv_bfloat16* Dl = which ? g_w2l : g_w1l;
    const int e = blockIdx.z;
    const int n0 = blockIdx.x * 32, k0 = blockIdx.y * 32;
    const float* src = W + (size_t)e * K * N;
    const int tx = threadIdx.x, ty = threadIdx.y;   // 32 x 8
    #pragma unroll
    for (int i = 0; i < 4; i++)
        s[ty + i*8][tx] = src[(size_t)(k0 + ty + i*8) * N + n0 + tx];
    __syncthreads();
    const size_t dbase = (size_t)e * N * K;
    #pragma unroll
    for (int i = 0; i < 4; i++) {
        const float v = s[tx][ty + i*8];
        const __nv_bfloat16 h = __float2bfloat16(v);
        const __nv_bfloat16 l = __float2bfloat16(v - __bfloat162float(h));
        const size_t o = dbase + (size_t)(n0 + ty + i*8) * K + k0 + tx;
        Dh[o] = h;  Dl[o] = l;
    }
}

// ---------------------------------------------------------------------------
// Batched GEMM: C[e][M][N] = A[e][M][K] @ B[e][N][K]^T  (3-term bf16 split)
// CTA 128x256, 256 threads (8 warps 2x4, warp tile 64x64), 3-stage cp.async.
// ---------------------------------------------------------------------------
__device__ __forceinline__ void load_stage(
    uint32_t sdst,
    const __nv_bfloat16* __restrict__ Ah, const __nv_bfloat16* __restrict__ Al,
    const __nv_bfloat16* __restrict__ Bh, const __nv_bfloat16* __restrict__ Bl,
    const int K, const int k0, const int tid)
{
    #pragma unroll
    for (int i = 0; i < 12; i++) {
        const int L = i * 256 + tid;          // 0..3071
        const int rid = L >> 2, q = L & 3;
        const __nv_bfloat16* src;
        uint32_t dst;
        if (rid < 128)      { src = Ah + (size_t)rid * K;                dst = sdst +         rid * 80; }
        else if (rid < 256) { const int r = rid - 128; src = Al + (size_t)r * K; dst = sdst + 10240 + r * 80; }
        else if (rid < 512) { const int r = rid - 256; src = Bh + (size_t)r * K; dst = sdst + 20480 + r * 80; }
        else                { const int r = rid - 512; src = Bl + (size_t)r * K; dst = sdst + 40960 + r * 80; }
        cp16(dst + q * 16, src + k0 + q * 8);
    }
}

__global__ void __launch_bounds__(256, 1)
gemm_mma(const int which, const int N, const int K)
{
    extern __shared__ char smem[];
    const uint32_t sb = smem_u32(smem);
    const int tid = threadIdx.x, wid = tid >> 5, lane = tid & 31;
    const int wm = wid & 1, wn = wid >> 1;          // 2 x 4 warp grid, warp 64x64
    const int e = blockIdx.z, bm = blockIdx.y * TM, bn = blockIdx.x * TN;

    const __nv_bfloat16 *gAh, *gAl, *gBh, *gBl;
    float* gC;
    if (which == 0) { gAh = g_axh; gAl = g_axl; gBh = g_w1h; gBl = g_w1l; gC = g_H; }
    else            { gAh = g_hgh; gAl = g_hgl; gBh = g_w2h; gBl = g_w2l; gC = g_eo; }

    const __nv_bfloat16* Ah = gAh + ((size_t)e * CAP + bm) * K;
    const __nv_bfloat16* Al = gAl + ((size_t)e * CAP + bm) * K;
    const __nv_bfloat16* Bh = gBh + ((size_t)e * N + bn) * K;
    const __nv_bfloat16* Bl = gBl + ((size_t)e * N + bn) * K;
    float* C = gC + (size_t)e * CAP * N;

    float acc[128];
    #pragma unroll
    for (int i = 0; i < 128; i++) acc[i] = 0.f;

    const int T = K / TK;
    load_stage(sb,           Ah, Al, Bh, Bl, K, 0,  tid);  CP_COMMIT();
    load_stage(sb + STAGE_B, Ah, Al, Bh, Bl, K, TK, tid);  CP_COMMIT();

    const int lmr = lane & 15;
    const int lmk = (lane >> 4) << 3;

    for (int t = 0; t < T; t++) {
        if (t + 1 < T) asm volatile("cp.async.wait_group 1;" ::: "memory");
        else           asm volatile("cp.async.wait_group 0;" ::: "memory");
        __syncthreads();   // all warps finished compute(t-1); stage t visible

        if (t + 2 < T) {   // refill slot (t+2)%3 == (t-1)%3 (safe after sync)
            load_stage(sb + ((t + 2) % 3) * STAGE_B, Ah, Al, Bh, Bl, K, (t + 2) * TK, tid);
            CP_COMMIT();
        }

        const uint32_t sst = sb + (t % 3) * STAGE_B;
        #pragma unroll
        for (int kk = 0; kk < 2; kk++) {
            const uint32_t koff = (kk * 16 + lmk) * 2;
            const uint32_t aA = sst + (wm * 64 + lmr) * 80 + koff;
            const uint32_t aB = sst + 20480 + (wn * 64 + lmr) * 80 + koff;

            uint32_t ah[16], bh[16], bt[16], q[4];
            // A hi: 4 m-tiles
            LDSM4(&ah[0],  aA);
            LDSM4(&ah[4],  aA + 1280);
            LDSM4(&ah[8],  aA + 2560);
            LDSM4(&ah[12], aA + 3840);
            // B hi: 8 n-tiles (4 x4-loads); n-tile j frag = {bh[2j], bh[2j+1]}
            #pragma unroll
            for (int u = 0; u < 4; u++) {
                LDSM4(q, aB + u * 1280);
                bh[4*u+0] = q[0]; bh[4*u+1] = q[2]; bh[4*u+2] = q[1]; bh[4*u+3] = q[3];
            }
            #pragma unroll
            for (int i = 0; i < 4; i++)
                #pragma unroll
                for (int j = 0; j < 8; j++)
                    MMA16816(&acc[(i*8+j)*4], &ah[i*4], bh[2*j], bh[2*j+1]);

            // B lo -> Ah x Bl
            #pragma unroll
            for (int u = 0; u < 4; u++) {
                LDSM4(q, aB + 20480 + u * 1280);
                bt[4*u+0] = q[0]; bt[4*u+1] = q[2]; bt[4*u+2] = q[1]; bt[4*u+3] = q[3];
            }
            #pragma unroll
            for (int i = 0; i < 4; i++)
                #pragma unroll
                for (int j = 0; j < 8; j++)
                    MMA16816(&acc[(i*8+j)*4], &ah[i*4], bt[2*j], bt[2*j+1]);

            // A lo (overwrite ah) -> Al x Bh
            LDSM4(&ah[0],  aA + 10240);
            LDSM4(&ah[4],  aA + 10240 + 1280);
            LDSM4(&ah[8],  aA + 10240 + 2560);
            LDSM4(&ah[12], aA + 10240 + 3840);
            #pragma unroll
            for (int i = 0; i < 4; i++)
                #pragma unroll
                for (int j = 0; j < 8; j++)
                    MMA16816(&acc[(i*8+j)*4], &ah[i*4], bh[2*j], bh[2*j+1]);
        }
    }

    // Epilogue: direct fp32 stores
    const int g = lane >> 2, tg = lane & 3;
    #pragma unroll
    for (int i = 0; i < 4; i++) {
        const int row = bm + wm * 64 + i * 16 + g;
        #pragma unroll
        for (int j = 0; j < 8; j++) {
            const int col = bn + wn * 64 + j * 8 + tg * 2;
            float* p = C + (size_t)row * N + col;
            const float* c = &acc[(i*8+j)*4];
            *(float2*)p           = make_float2(c[0], c[1]);
            *(float2*)(p + 8 * N) = make_float2(c[2], c[3]);
        }
    }
}

// ---------------------------------------------------------------------------
// SwiGLU + bf16 hi/lo split:  hg = silu(H[:, :1536]) * H[:, 1536:]
// ---------------------------------------------------------------------------
__global__ void swiglu_split() {
    const size_t row = blockIdx.x;
    const int c = threadIdx.x * 4;
    const float4 a = *(const float4*)&g_H[row * DFF + c];
    const float4 g = *(const float4*)&g_H[row * DFF + DH + c];
    float4 o;
    o.x = (a.x / (1.f + expf(-a.x))) * g.x;
    o.y = (a.y / (1.f + expf(-a.y))) * g.y;
    o.z = (a.z / (1.f + expf(-a.z))) * g.z;
    o.w = (a.w / (1.f + expf(-a.w))) * g.w;
    split4(o, &g_hgh[row * DH + c], &g_hgl[row * DH + c]);
}

// ---------------------------------------------------------------------------
// Combine: out[n] = w0*eo[e0,p0] + w1*eo[e1,p1]
// ---------------------------------------------------------------------------
__global__ void combine_kernel(float* __restrict__ out) {
    const int n = blockIdx.x;
    const int s0 = 2 * n;
    float w0 = g_sw[s0], w1 = g_sw[s0 + 1];
    int   p0 = g_sp[s0], p1 = g_sp[s0 + 1];
    const int e0 = g_se[s0], e1 = g_se[s0 + 1];
    if (p0 < 0) { w0 = 0.f; p0 = 0; }
    if (p1 < 0) { w1 = 0.f; p1 = 0; }
    const float4 a = ((const float4*)(g_eo + ((size_t)e0 * CAP + p0) * DM))[threadIdx.x];
    const float4 b = ((const float4*)(g_eo + ((size_t)e1 * CAP + p1) * DM))[threadIdx.x];
    float4 o;
    o.x = w0 * a.x + w1 * b.x;
    o.y = w0 * a.y + w1 * b.y;
    o.z = w0 * a.z + w1 * b.z;
    o.w = w0 * a.w + w1 * b.w;
    ((float4*)(out + (size_t)n * DM))[threadIdx.x] = o;
}

// ---------------------------------------------------------------------------
extern "C" void kernel_launch(void* const* d_in, const int* in_sizes, int n_in,
                              void* d_out, int out_size) {
    const float *x = nullptr, *wg = nullptr, *cfc = nullptr, *cpr = nullptr;
    for (int i = 0; i < n_in; i++) {
        switch (in_sizes[i]) {
            case 16777216: x   = (const float*)d_in[i]; break;  // [8,2048,1024]
            case 8192:     wg  = (const float*)d_in[i]; break;  // [1024,8]
            case 25165824: cfc = (const float*)d_in[i]; break;  // [8,1024,3072]
            case 12582912: cpr = (const float*)d_in[i]; break;  // [8,1536,1024]
        }
    }
    float* out = (float*)d_out;

    cudaFuncSetAttribute(gemm_mma, cudaFuncAttributeMaxDynamicSharedMemorySize, GEMM_SMEM);

    gate_kernel  <<<N_TOK / 4, 128>>>(x, wg);
    count_kernel <<<NBLK, 1024>>>();
    scan_kernel  <<<1, NE>>>();
    pos_kernel   <<<NBLK, 1024>>>();
    scatter_split<<<NSLOT, 256>>>(x);

    wsplit_kernel<<<dim3(DFF / 32, DM / 32, NE), dim3(32, 8)>>>(cfc, 0, DM, DFF);  // W1
    wsplit_kernel<<<dim3(DM / 32, DH / 32, NE), dim3(32, 8)>>>(cpr, 1, DH, DM);    // W2

    gemm_mma<<<dim3(DFF / TN, CAP / TM, NE), 256, GEMM_SMEM>>>(0, DFF, DM);   // H = X @ W1^T
    swiglu_split<<<NE * CAP, DH / 4>>>();
    gemm_mma<<<dim3(DM / TN, CAP / TM, NE), 256, GEMM_SMEM>>>(1, DM, DH);     // O = HG @ W2^T

    combine_kernel<<<N_TOK, 256>>>(out);
}

// round 7
// speedup vs baseline: 2.8737x; 1.3995x over previous
#include <cuda_runtime.h>
#include <cuda_fp16.h>
#include <stdint.h>
#include <math.h>

// ---------------------------------------------------------------------------
// MoE: gate -> top2 route -> capacity dispatch -> 8x SwiGLU expert MLP -> combine
// Expert GEMMs: mma.sync fp16, 2-term split: A_fp16 * (Bh + Bl), fp32 acc.
//   Weights exact to ~22 bits (hi+lo fp16); activations rounded to fp16 (2^-12).
//   Legacy mma.sync on sm_100 is issue-bound (~13.7cyc/MMA/SMSP) -> fewer MMAs.
// ---------------------------------------------------------------------------

#define N_TOK   16384
#define DM      1024
#define NE      8
#define CAP     4096
#define DFF     3072
#define DH      1536
#define NSLOT   (N_TOK * 2)
#define NBLK    32

// GEMM tiling
#define TM      128
#define TN      256
#define TK      32
#define STAGE_B 51200          // A: 128*80  +  Bh,Bl: 2*256*80
#define GEMM_SMEM (3 * STAGE_B)

// ---- scratch (device globals: allocation-free rule) ----
__device__ float g_H [(size_t)NE * CAP * DFF];     // fc output (fp32)
__device__ float g_eo[(size_t)NE * CAP * DM];      // expert output (fp32)
__device__ __half g_ax[(size_t)NE * CAP * DM];     // dispatched x (fp16)
__device__ __half g_hg[(size_t)NE * CAP * DH];     // swiglu out (fp16)
__device__ __half g_w1h[(size_t)NE * DFF * DM];    // W1^T [E][3072][1024] hi
__device__ __half g_w1l[(size_t)NE * DFF * DM];    //                      lo
__device__ __half g_w2h[(size_t)NE * DM * DH];     // W2^T [E][1024][1536] hi
__device__ __half g_w2l[(size_t)NE * DM * DH];     //                      lo
__device__ int   g_se[NSLOT];
__device__ float g_sw[NSLOT];
__device__ int   g_sp[NSLOT];
__device__ int   g_bcnt[NBLK * NE];
__device__ int   g_boff[NBLK * NE];

// ---------------------------------------------------------------------------
// helpers
// ---------------------------------------------------------------------------
__device__ __forceinline__ uint32_t smem_u32(const void* p) {
    uint32_t a;
    asm("{ .reg .u64 t; cvta.to.shared.u64 t, %1; cvt.u32.u64 %0, t; }"
        : "=r"(a) : "l"(p));
    return a;
}
__device__ __forceinline__ void cp16(uint32_t dst, const void* src) {
    asm volatile("cp.async.cg.shared.global [%0], [%1], 16;" :: "r"(dst), "l"(src));
}
#define CP_COMMIT() asm volatile("cp.async.commit_group;" ::: "memory")

#define LDSM4(v, addr) \
    asm volatile("ldmatrix.sync.aligned.m8n8.x4.shared.b16 {%0,%1,%2,%3}, [%4];" \
        : "=r"((v)[0]), "=r"((v)[1]), "=r"((v)[2]), "=r"((v)[3]) : "r"(addr))

#define MMA16816(c, a, b0, b1) \
    asm volatile("mma.sync.aligned.m16n8k16.row.col.f32.f16.f16.f32 " \
        "{%0,%1,%2,%3}, {%4,%5,%6,%7}, {%8,%9}, {%0,%1,%2,%3};" \
        : "+f"((c)[0]), "+f"((c)[1]), "+f"((c)[2]), "+f"((c)[3]) \
        : "r"((a)[0]), "r"((a)[1]), "r"((a)[2]), "r"((a)[3]), "r"(b0), "r"(b1))

// ---------------------------------------------------------------------------
// Gate: logits -> softmax -> top2 (ties: lowest index)
// ---------------------------------------------------------------------------
__global__ void gate_kernel(const float* __restrict__ x, const float* __restrict__ wg) {
    __shared__ float wgs[NE][DM];
    const int tid = threadIdx.x;
    for (int i = tid; i < NE * DM; i += blockDim.x)
        wgs[i & 7][i >> 3] = wg[i];
    __syncthreads();

    const int warp = tid >> 5, lane = tid & 31;
    const int n = blockIdx.x * 4 + warp;

    float acc[NE];
    #pragma unroll
    for (int e = 0; e < NE; e++) acc[e] = 0.f;
    const float* xr = x + (size_t)n * DM;
    for (int j = lane; j < DM; j += 32) {
        const float xv = xr[j];
        #pragma unroll
        for (int e = 0; e < NE; e++) acc[e] += xv * wgs[e][j];
    }
    #pragma unroll
    for (int off = 16; off; off >>= 1)
        #pragma unroll
        for (int e = 0; e < NE; e++)
            acc[e] += __shfl_xor_sync(0xffffffffu, acc[e], off);

    if (lane == 0) {
        float m = acc[0];
        #pragma unroll
        for (int e = 1; e < NE; e++) m = fmaxf(m, acc[e]);
        float p[NE], s = 0.f;
        #pragma unroll
        for (int e = 0; e < NE; e++) { p[e] = expf(acc[e] - m); s += p[e]; }
        const float inv = 1.f / s;
        #pragma unroll
        for (int e = 0; e < NE; e++) p[e] *= inv;
        int e1 = 0;
        #pragma unroll
        for (int e = 1; e < NE; e++) if (p[e] > p[e1]) e1 = e;
        int e2 = (e1 == 0) ? 1 : 0;
        #pragma unroll
        for (int e = 0; e < NE; e++) if (e != e1 && p[e] > p[e2]) e2 = e;
        g_se[2*n]   = e1;  g_sw[2*n]   = p[e1];
        g_se[2*n+1] = e2;  g_sw[2*n+1] = p[e2];
    }
}

// ---------------------------------------------------------------------------
// Rank: per-expert exclusive position over slots in flat order
// ---------------------------------------------------------------------------
__global__ void count_kernel() {
    __shared__ int c[NE];
    if (threadIdx.x < NE) c[threadIdx.x] = 0;
    __syncthreads();
    atomicAdd(&c[g_se[blockIdx.x * 1024 + threadIdx.x]], 1);
    __syncthreads();
    if (threadIdx.x < NE) g_bcnt[blockIdx.x * NE + threadIdx.x] = c[threadIdx.x];
}
__global__ void scan_kernel() {
    const int e = threadIdx.x;
    int run = 0;
    for (int b = 0; b < NBLK; b++) { g_boff[b * NE + e] = run; run += g_bcnt[b * NE + e]; }
}
__global__ void pos_kernel() {
    __shared__ int el[1024];
    const int t = threadIdx.x;
    const int s = blockIdx.x * 1024 + t;
    const int e = g_se[s];
    el[t] = e;
    __syncthreads();
    int r = g_boff[blockIdx.x * NE + e];
    for (int j = 0; j < t; j++) r += (el[j] == e);
    g_sp[s] = (r < CAP) ? r : -1;
}

// ---------------------------------------------------------------------------
// Scatter: x rows -> fp16 into exp slot
// ---------------------------------------------------------------------------
__global__ void scatter_fp16(const float* __restrict__ x) {
    const int s = blockIdx.x;
    const int p = g_sp[s];
    if (p < 0) return;
    const int e = g_se[s];
    const int tok = s >> 1;
    const float4 v = ((const float4*)(x + (size_t)tok * DM))[threadIdx.x];
    __half h[4] = { __float2half(v.x), __float2half(v.y),
                    __float2half(v.z), __float2half(v.w) };
    *(uint2*)&g_ax[((size_t)e * CAP + p) * DM + threadIdx.x * 4] = *(uint2*)h;
}

// ---------------------------------------------------------------------------
// Weight transpose + fp16 hi/lo split: W[e][K][N] -> Wt hi/lo [e][N][K]
// ---------------------------------------------------------------------------
__global__ void wsplit_kernel(const float* __restrict__ W, const int which,
                              const int K, const int N) {
    __shared__ float s[32][33];
    __half* Dh = which ? g_w2h : g_w1h;
    __half* Dl = which ? g_w2l : g_w1l;
    const int e = blockIdx.z;
    const int n0 = blockIdx.x * 32, k0 = blockIdx.y * 32;
    const float* src = W + (size_t)e * K * N;
    const int tx = threadIdx.x, ty = threadIdx.y;   // 32 x 8
    #pragma unroll
    for (int i = 0; i < 4; i++)
        s[ty + i*8][tx] = src[(size_t)(k0 + ty + i*8) * N + n0 + tx];
    __syncthreads();
    const size_t dbase = (size_t)e * N * K;
    #pragma unroll
    for (int i = 0; i < 4; i++) {
        const float v = s[tx][ty + i*8];
        const __half h = __float2half(v);
        const __half l = __float2half(v - __half2float(h));
        const size_t o = dbase + (size_t)(n0 + ty + i*8) * K + k0 + tx;
        Dh[o] = h;  Dl[o] = l;
    }
}

// ---------------------------------------------------------------------------
// Batched GEMM: C[e][M][N] = A[e][M][K] @ (Bh+Bl)[e][N][K]^T   (fp16, fp32 acc)
// CTA 128x256, 256 threads (8 warps 2x4, warp tile 64x64), 3-stage cp.async.
// ---------------------------------------------------------------------------
__device__ __forceinline__ void load_stage(
    uint32_t sdst,
    const __half* __restrict__ A,
    const __half* __restrict__ Bh, const __half* __restrict__ Bl,
    const int K, const int k0, const int tid)
{
    // 640 padded rows (A:128, Bh:256, Bl:256), 4 x 16B quads per row
    #pragma unroll
    for (int i = 0; i < 10; i++) {
        const int L = i * 256 + tid;          // 0..2559
        const int rid = L >> 2, q = L & 3;
        const __half* src;
        uint32_t dst;
        if (rid < 128)      { src = A  + (size_t)rid * K;                dst = sdst +         rid * 80; }
        else if (rid < 384) { const int r = rid - 128; src = Bh + (size_t)r * K; dst = sdst + 10240 + r * 80; }
        else                { const int r = rid - 384; src = Bl + (size_t)r * K; dst = sdst + 30720 + r * 80; }
        cp16(dst + q * 16, src + k0 + q * 8);
    }
}

__global__ void __launch_bounds__(256, 1)
gemm_mma(const int which, const int N, const int K)
{
    extern __shared__ char smem[];
    const uint32_t sb = smem_u32(smem);
    const int tid = threadIdx.x, wid = tid >> 5, lane = tid & 31;
    const int wm = wid & 1, wn = wid >> 1;          // 2 x 4 warp grid, warp 64x64
    const int e = blockIdx.z, bm = blockIdx.y * TM, bn = blockIdx.x * TN;

    const __half *gA, *gBh, *gBl;
    float* gC;
    if (which == 0) { gA = g_ax; gBh = g_w1h; gBl = g_w1l; gC = g_H; }
    else            { gA = g_hg; gBh = g_w2h; gBl = g_w2l; gC = g_eo; }

    const __half* A  = gA  + ((size_t)e * CAP + bm) * K;
    const __half* Bh = gBh + ((size_t)e * N + bn) * K;
    const __half* Bl = gBl + ((size_t)e * N + bn) * K;
    float* C = gC + (size_t)e * CAP * N;

    float acc[128];
    #pragma unroll
    for (int i = 0; i < 128; i++) acc[i] = 0.f;

    const int T = K / TK;
    load_stage(sb,           A, Bh, Bl, K, 0,  tid);  CP_COMMIT();
    load_stage(sb + STAGE_B, A, Bh, Bl, K, TK, tid);  CP_COMMIT();

    const int lmr = lane & 15;
    const int lmk = (lane >> 4) << 3;

    for (int t = 0; t < T; t++) {
        if (t + 1 < T) asm volatile("cp.async.wait_group 1;" ::: "memory");
        else           asm volatile("cp.async.wait_group 0;" ::: "memory");
        __syncthreads();   // all warps finished compute(t-1); stage t visible

        if (t + 2 < T) {   // refill slot (t+2)%3 == (t-1)%3 (safe after sync)
            load_stage(sb + ((t + 2) % 3) * STAGE_B, A, Bh, Bl, K, (t + 2) * TK, tid);
            CP_COMMIT();
        }

        const uint32_t sst = sb + (t % 3) * STAGE_B;
        #pragma unroll
        for (int kk = 0; kk < 2; kk++) {
            const uint32_t koff = (kk * 16 + lmk) * 2;
            const uint32_t aA = sst + (wm * 64 + lmr) * 80 + koff;
            const uint32_t aB = sst + 10240 + (wn * 64 + lmr) * 80 + koff;

            uint32_t ah[16], bh[16], bl[16], q[4];
            // A: 4 m-tiles
            LDSM4(&ah[0],  aA);
            LDSM4(&ah[4],  aA + 1280);
            LDSM4(&ah[8],  aA + 2560);
            LDSM4(&ah[12], aA + 3840);
            // B hi: 8 n-tiles (4 x4-loads); n-tile j frag = {bh[2j], bh[2j+1]}
            #pragma unroll
            for (int u = 0; u < 4; u++) {
                LDSM4(q, aB + u * 1280);
                bh[4*u+0] = q[0]; bh[4*u+1] = q[2]; bh[4*u+2] = q[1]; bh[4*u+3] = q[3];
            }
            #pragma unroll
            for (int i = 0; i < 4; i++)
                #pragma unroll
                for (int j = 0; j < 8; j++)
                    MMA16816(&acc[(i*8+j)*4], &ah[i*4], bh[2*j], bh[2*j+1]);

            // B lo
            #pragma unroll
            for (int u = 0; u < 4; u++) {
                LDSM4(q, aB + 20480 + u * 1280);
                bl[4*u+0] = q[0]; bl[4*u+1] = q[2]; bl[4*u+2] = q[1]; bl[4*u+3] = q[3];
            }
            #pragma unroll
            for (int i = 0; i < 4; i++)
                #pragma unroll
                for (int j = 0; j < 8; j++)
                    MMA16816(&acc[(i*8+j)*4], &ah[i*4], bl[2*j], bl[2*j+1]);
        }
    }

    // Epilogue: direct fp32 stores
    const int g = lane >> 2, tg = lane & 3;
    #pragma unroll
    for (int i = 0; i < 4; i++) {
        const int row = bm + wm * 64 + i * 16 + g;
        #pragma unroll
        for (int j = 0; j < 8; j++) {
            const int col = bn + wn * 64 + j * 8 + tg * 2;
            float* p = C + (size_t)row * N + col;
            const float* c = &acc[(i*8+j)*4];
            *(float2*)p           = make_float2(c[0], c[1]);
            *(float2*)(p + 8 * N) = make_float2(c[2], c[3]);
        }
    }
}

// ---------------------------------------------------------------------------
// SwiGLU -> fp16:  hg = silu(H[:, :1536]) * H[:, 1536:]
// ---------------------------------------------------------------------------
__global__ void swiglu_fp16() {
    const size_t row = blockIdx.x;
    const int c = threadIdx.x * 4;
    const float4 a = *(const float4*)&g_H[row * DFF + c];
    const float4 g = *(const float4*)&g_H[row * DFF + DH + c];
    __half h[4];
    h[0] = __float2half((a.x / (1.f + expf(-a.x))) * g.x);
    h[1] = __float2half((a.y / (1.f + expf(-a.y))) * g.y);
    h[2] = __float2half((a.z / (1.f + expf(-a.z))) * g.z);
    h[3] = __float2half((a.w / (1.f + expf(-a.w))) * g.w);
    *(uint2*)&g_hg[row * DH + c] = *(uint2*)h;
}

// ---------------------------------------------------------------------------
// Combine: out[n] = w0*eo[e0,p0] + w1*eo[e1,p1]
// ---------------------------------------------------------------------------
__global__ void combine_kernel(float* __restrict__ out) {
    const int n = blockIdx.x;
    const int s0 = 2 * n;
    float w0 = g_sw[s0], w1 = g_sw[s0 + 1];
    int   p0 = g_sp[s0], p1 = g_sp[s0 + 1];
    const int e0 = g_se[s0], e1 = g_se[s0 + 1];
    if (p0 < 0) { w0 = 0.f; p0 = 0; }
    if (p1 < 0) { w1 = 0.f; p1 = 0; }
    const float4 a = ((const float4*)(g_eo + ((size_t)e0 * CAP + p0) * DM))[threadIdx.x];
    const float4 b = ((const float4*)(g_eo + ((size_t)e1 * CAP + p1) * DM))[threadIdx.x];
    float4 o;
    o.x = w0 * a.x + w1 * b.x;
    o.y = w0 * a.y + w1 * b.y;
    o.z = w0 * a.z + w1 * b.z;
    o.w = w0 * a.w + w1 * b.w;
    ((float4*)(out + (size_t)n * DM))[threadIdx.x] = o;
}

// ---------------------------------------------------------------------------
extern "C" void kernel_launch(void* const* d_in, const int* in_sizes, int n_in,
                              void* d_out, int out_size) {
    const float *x = nullptr, *wg = nullptr, *cfc = nullptr, *cpr = nullptr;
    for (int i = 0; i < n_in; i++) {
        switch (in_sizes[i]) {
            case 16777216: x   = (const float*)d_in[i]; break;  // [8,2048,1024]
            case 8192:     wg  = (const float*)d_in[i]; break;  // [1024,8]
            case 25165824: cfc = (const float*)d_in[i]; break;  // [8,1024,3072]
            case 12582912: cpr = (const float*)d_in[i]; break;  // [8,1536,1024]
        }
    }
    float* out = (float*)d_out;

    cudaFuncSetAttribute(gemm_mma, cudaFuncAttributeMaxDynamicSharedMemorySize, GEMM_SMEM);

    gate_kernel  <<<N_TOK / 4, 128>>>(x, wg);
    count_kernel <<<NBLK, 1024>>>();
    scan_kernel  <<<1, NE>>>();
    pos_kernel   <<<NBLK, 1024>>>();
    scatter_fp16 <<<NSLOT, 256>>>(x);

    wsplit_kernel<<<dim3(DFF / 32, DM / 32, NE), dim3(32, 8)>>>(cfc, 0, DM, DFF);  // W1
    wsplit_kernel<<<dim3(DM / 32, DH / 32, NE), dim3(32, 8)>>>(cpr, 1, DH, DM);    // W2

    gemm_mma<<<dim3(DFF / TN, CAP / TM, NE), 256, GEMM_SMEM>>>(0, DFF, DM);   // H = X @ W1^T
    swiglu_fp16<<<NE * CAP, DH / 4>>>();
    gemm_mma<<<dim3(DM / TN, CAP / TM, NE), 256, GEMM_SMEM>>>(1, DM, DH);     // O = HG @ W2^T

    combine_kernel<<<N_TOK, 256>>>(out);
}

// round 8
// speedup vs baseline: 4.5474x; 1.5824x over previous
#include <cuda_runtime.h>
#include <cuda_fp16.h>
#include <stdint.h>
#include <math.h>

// ---------------------------------------------------------------------------
// MoE: gate -> top2 route -> capacity dispatch -> 8x SwiGLU expert MLP -> combine
// Expert GEMMs: mma.sync fp16 (single term, fp32 acc), legacy pipe rt=16cyc/SMSP
// GEMM1 epilogue fuses SwiGLU via interleaved W1^T (row 2j=a_j, row 2j+1=g_j).
// ---------------------------------------------------------------------------

#define N_TOK   16384
#define DM      1024
#define NE      8
#define CAP     4096
#define DFF     3072
#define DH      1536
#define NSLOT   (N_TOK * 2)
#define NBLK    32

// GEMM tiling
#define TM      128
#define TN      256
#define TK      32
#define STAGE_B 30720          // A: 128*80  +  B: 256*80
#define GEMM_SMEM (3 * STAGE_B)

// ---- scratch (device globals: allocation-free rule) ----
__device__ float  g_eo[(size_t)NE * CAP * DM];     // expert output (fp32)
__device__ __half g_ax[(size_t)NE * CAP * DM];     // dispatched x (fp16)
__device__ __half g_hg[(size_t)NE * CAP * DH];     // swiglu out (fp16)
__device__ __half g_w1[(size_t)NE * DFF * DM];     // W1^T interleaved [E][3072][1024]
__device__ __half g_w2[(size_t)NE * DM * DH];      // W2^T [E][1024][1536]
__device__ int   g_se[NSLOT];
__device__ float g_sw[NSLOT];
__device__ int   g_sp[NSLOT];
__device__ int   g_bcnt[NBLK * NE];
__device__ int   g_boff[NBLK * NE];

// ---------------------------------------------------------------------------
// helpers
// ---------------------------------------------------------------------------
__device__ __forceinline__ uint32_t smem_u32(const void* p) {
    uint32_t a;
    asm("{ .reg .u64 t; cvta.to.shared.u64 t, %1; cvt.u32.u64 %0, t; }"
        : "=r"(a) : "l"(p));
    return a;
}
__device__ __forceinline__ void cp16(uint32_t dst, const void* src) {
    asm volatile("cp.async.cg.shared.global [%0], [%1], 16;" :: "r"(dst), "l"(src));
}
#define CP_COMMIT() asm volatile("cp.async.commit_group;" ::: "memory")

#define LDSM4(v, addr) \
    asm volatile("ldmatrix.sync.aligned.m8n8.x4.shared.b16 {%0,%1,%2,%3}, [%4];" \
        : "=r"((v)[0]), "=r"((v)[1]), "=r"((v)[2]), "=r"((v)[3]) : "r"(addr))

#define MMA16816(c, a, b0, b1) \
    asm volatile("mma.sync.aligned.m16n8k16.row.col.f32.f16.f16.f32 " \
        "{%0,%1,%2,%3}, {%4,%5,%6,%7}, {%8,%9}, {%0,%1,%2,%3};" \
        : "+f"((c)[0]), "+f"((c)[1]), "+f"((c)[2]), "+f"((c)[3]) \
        : "r"((a)[0]), "r"((a)[1]), "r"((a)[2]), "r"((a)[3]), "r"(b0), "r"(b1))

// ---------------------------------------------------------------------------
// Gate: logits -> softmax -> top2 (ties: lowest index)
// ---------------------------------------------------------------------------
__global__ void gate_kernel(const float* __restrict__ x, const float* __restrict__ wg) {
    __shared__ float wgs[NE][DM];
    const int tid = threadIdx.x;
    for (int i = tid; i < NE * DM; i += blockDim.x)
        wgs[i & 7][i >> 3] = wg[i];
    __syncthreads();

    const int warp = tid >> 5, lane = tid & 31;
    const int n = blockIdx.x * 4 + warp;

    float acc[NE];
    #pragma unroll
    for (int e = 0; e < NE; e++) acc[e] = 0.f;
    const float* xr = x + (size_t)n * DM;
    for (int j = lane; j < DM; j += 32) {
        const float xv = xr[j];
        #pragma unroll
        for (int e = 0; e < NE; e++) acc[e] += xv * wgs[e][j];
    }
    #pragma unroll
    for (int off = 16; off; off >>= 1)
        #pragma unroll
        for (int e = 0; e < NE; e++)
            acc[e] += __shfl_xor_sync(0xffffffffu, acc[e], off);

    if (lane == 0) {
        float m = acc[0];
        #pragma unroll
        for (int e = 1; e < NE; e++) m = fmaxf(m, acc[e]);
        float p[NE], s = 0.f;
        #pragma unroll
        for (int e = 0; e < NE; e++) { p[e] = expf(acc[e] - m); s += p[e]; }
        const float inv = 1.f / s;
        #pragma unroll
        for (int e = 0; e < NE; e++) p[e] *= inv;
        int e1 = 0;
        #pragma unroll
        for (int e = 1; e < NE; e++) if (p[e] > p[e1]) e1 = e;
        int e2 = (e1 == 0) ? 1 : 0;
        #pragma unroll
        for (int e = 0; e < NE; e++) if (e != e1 && p[e] > p[e2]) e2 = e;
        g_se[2*n]   = e1;  g_sw[2*n]   = p[e1];
        g_se[2*n+1] = e2;  g_sw[2*n+1] = p[e2];
    }
}

// ---------------------------------------------------------------------------
// Rank: per-expert exclusive position over slots in flat order
// ---------------------------------------------------------------------------
__global__ void count_kernel() {
    __shared__ int c[NE];
    if (threadIdx.x < NE) c[threadIdx.x] = 0;
    __syncthreads();
    atomicAdd(&c[g_se[blockIdx.x * 1024 + threadIdx.x]], 1);
    __syncthreads();
    if (threadIdx.x < NE) g_bcnt[blockIdx.x * NE + threadIdx.x] = c[threadIdx.x];
}
__global__ void scan_kernel() {
    const int e = threadIdx.x;
    int run = 0;
    for (int b = 0; b < NBLK; b++) { g_boff[b * NE + e] = run; run += g_bcnt[b * NE + e]; }
}
__global__ void pos_kernel() {
    __shared__ int el[1024];
    const int t = threadIdx.x;
    const int s = blockIdx.x * 1024 + t;
    const int e = g_se[s];
    el[t] = e;
    __syncthreads();
    int r = g_boff[blockIdx.x * NE + e];
    for (int j = 0; j < t; j++) r += (el[j] == e);
    g_sp[s] = (r < CAP) ? r : -1;
}

// ---------------------------------------------------------------------------
// Scatter: x rows -> fp16 into exp slot
// ---------------------------------------------------------------------------
__global__ void scatter_fp16(const float* __restrict__ x) {
    const int s = blockIdx.x;
    const int p = g_sp[s];
    if (p < 0) return;
    const int e = g_se[s];
    const int tok = s >> 1;
    const float4 v = ((const float4*)(x + (size_t)tok * DM))[threadIdx.x];
    __half h[4] = { __float2half(v.x), __float2half(v.y),
                    __float2half(v.z), __float2half(v.w) };
    *(uint2*)&g_ax[((size_t)e * CAP + p) * DM + threadIdx.x * 4] = *(uint2*)h;
}

// ---------------------------------------------------------------------------
// Weight transpose -> fp16. which==0 (W1): interleave dest rows so that
//   dest row 2j   = fc column j         (a / silu input)
//   dest row 2j+1 = fc column j + 1536  (g / gate input)
// which==1 (W2): plain transpose.
// ---------------------------------------------------------------------------
__global__ void wsplit_kernel(const float* __restrict__ W, const int which,
                              const int K, const int N) {
    __shared__ float s[32][33];
    __half* D = which ? g_w2 : g_w1;
    const int e = blockIdx.z;
    const int n0 = blockIdx.x * 32, k0 = blockIdx.y * 32;
    const float* src = W + (size_t)e * K * N;
    const int tx = threadIdx.x, ty = threadIdx.y;   // 32 x 8

    // smem column c holds source column scol(c)
    int scol;
    if (which == 0) scol = (tx < 16) ? (n0 / 2 + tx) : (n0 / 2 + DH + (tx - 16));
    else            scol = n0 + tx;

    #pragma unroll
    for (int i = 0; i < 4; i++)
        s[ty + i*8][tx] = src[(size_t)(k0 + ty + i*8) * N + scol];
    __syncthreads();

    const size_t dbase = (size_t)e * N * K;
    #pragma unroll
    for (int i = 0; i < 4; i++) {
        const int r = ty + i*8;                       // dest row offset in tile
        const int c = which == 0 ? ((r & 1) ? 16 + (r >> 1) : (r >> 1)) : r;
        D[dbase + (size_t)(n0 + r) * K + k0 + tx] = __float2half(s[tx][c]);
    }
}

// ---------------------------------------------------------------------------
// Batched GEMM: C[e][M][N] = A[e][M][K] @ B[e][N][K]^T   (fp16 x fp16, fp32 acc)
// CTA 128x256, 256 threads (8 warps 2x4, warp tile 64x64), 3-stage cp.async.
// which==0: epilogue fuses SwiGLU on interleaved column pairs -> g_hg (fp16).
// which==1: plain fp32 store -> g_eo.
// ---------------------------------------------------------------------------
__device__ __forceinline__ void load_stage(
    uint32_t sdst,
    const __half* __restrict__ A, const __half* __restrict__ B,
    const int K, const int k0, const int tid)
{
    #pragma unroll
    for (int i = 0; i < 6; i++) {
        const int L = i * 256 + tid;          // 0..1535
        const int rid = L >> 2, q = L & 3;
        const __half* src;
        uint32_t dst;
        if (rid < 128) { src = A + (size_t)rid * K;                 dst = sdst +         rid * 80; }
        else           { const int r = rid - 128; src = B + (size_t)r * K; dst = sdst + 10240 + r * 80; }
        cp16(dst + q * 16, src + k0 + q * 8);
    }
}

__global__ void __launch_bounds__(256, 1)
gemm_mma(const int which, const int N, const int K)
{
    extern __shared__ char smem[];
    const uint32_t sb = smem_u32(smem);
    const int tid = threadIdx.x, wid = tid >> 5, lane = tid & 31;
    const int wm = wid & 1, wn = wid >> 1;          // 2 x 4 warp grid, warp 64x64
    const int e = blockIdx.z, bm = blockIdx.y * TM, bn = blockIdx.x * TN;

    const __half *gA, *gB;
    if (which == 0) { gA = g_ax; gB = g_w1; }
    else            { gA = g_hg; gB = g_w2; }

    const __half* A = gA + ((size_t)e * CAP + bm) * K;
    const __half* B = gB + ((size_t)e * N + bn) * K;

    float acc[128];
    #pragma unroll
    for (int i = 0; i < 128; i++) acc[i] = 0.f;

    const int T = K / TK;
    load_stage(sb,           A, B, K, 0,  tid);  CP_COMMIT();
    load_stage(sb + STAGE_B, A, B, K, TK, tid);  CP_COMMIT();

    const int lmr = lane & 15;
    const int lmk = (lane >> 4) << 3;

    for (int t = 0; t < T; t++) {
        if (t + 1 < T) asm volatile("cp.async.wait_group 1;" ::: "memory");
        else           asm volatile("cp.async.wait_group 0;" ::: "memory");
        __syncthreads();   // all warps finished compute(t-1); stage t visible

        if (t + 2 < T) {   // refill slot (t+2)%3 == (t-1)%3 (safe after sync)
            load_stage(sb + ((t + 2) % 3) * STAGE_B, A, B, K, (t + 2) * TK, tid);
            CP_COMMIT();
        }

        const uint32_t sst = sb + (t % 3) * STAGE_B;
        #pragma unroll
        for (int kk = 0; kk < 2; kk++) {
            const uint32_t koff = (kk * 16 + lmk) * 2;
            const uint32_t aA = sst + (wm * 64 + lmr) * 80 + koff;
            const uint32_t aB = sst + 10240 + (wn * 64 + lmr) * 80 + koff;

            uint32_t ah[16], bh[16], q[4];
            LDSM4(&ah[0],  aA);
            LDSM4(&ah[4],  aA + 1280);
            LDSM4(&ah[8],  aA + 2560);
            LDSM4(&ah[12], aA + 3840);
            #pragma unroll
            for (int u = 0; u < 4; u++) {
                LDSM4(q, aB + u * 1280);
                bh[4*u+0] = q[0]; bh[4*u+1] = q[2]; bh[4*u+2] = q[1]; bh[4*u+3] = q[3];
            }
            #pragma unroll
            for (int i = 0; i < 4; i++)
                #pragma unroll
                for (int j = 0; j < 8; j++)
                    MMA16816(&acc[(i*8+j)*4], &ah[i*4], bh[2*j], bh[2*j+1]);
        }
    }

    const int g = lane >> 2, tg = lane & 3;
    if (which == 0) {
        // Fused SwiGLU: interleaved cols -> (c0,c1)=(a,g) at row, (c2,c3) at row+8
        __half* HG = g_hg + (size_t)e * CAP * DH;
        #pragma unroll
        for (int i = 0; i < 4; i++) {
            const int row = bm + wm * 64 + i * 16 + g;
            #pragma unroll
            for (int j = 0; j < 8; j++) {
                const int colh = (bn >> 1) + wn * 32 + j * 4 + tg;
                const float* c = &acc[(i*8+j)*4];
                const float h0 = (c[0] / (1.f + expf(-c[0]))) * c[1];
                const float h1 = (c[2] / (1.f + expf(-c[2]))) * c[3];
                HG[(size_t)row * DH + colh]       = __float2half(h0);
                HG[(size_t)(row + 8) * DH + colh] = __float2half(h1);
            }
        }
    } else {
        float* C = g_eo + (size_t)e * CAP * N;
        #pragma unroll
        for (int i = 0; i < 4; i++) {
            const int row = bm + wm * 64 + i * 16 + g;
            #pragma unroll
            for (int j = 0; j < 8; j++) {
                const int col = bn + wn * 64 + j * 8 + tg * 2;
                float* p = C + (size_t)row * N + col;
                const float* c = &acc[(i*8+j)*4];
                *(float2*)p           = make_float2(c[0], c[1]);
                *(float2*)(p + 8 * N) = make_float2(c[2], c[3]);
            }
        }
    }
}

// ---------------------------------------------------------------------------
// Combine: out[n] = w0*eo[e0,p0] + w1*eo[e1,p1]
// ---------------------------------------------------------------------------
__global__ void combine_kernel(float* __restrict__ out) {
    const int n = blockIdx.x;
    const int s0 = 2 * n;
    float w0 = g_sw[s0], w1 = g_sw[s0 + 1];
    int   p0 = g_sp[s0], p1 = g_sp[s0 + 1];
    const int e0 = g_se[s0], e1 = g_se[s0 + 1];
    if (p0 < 0) { w0 = 0.f; p0 = 0; }
    if (p1 < 0) { w1 = 0.f; p1 = 0; }
    const float4 a = ((const float4*)(g_eo + ((size_t)e0 * CAP + p0) * DM))[threadIdx.x];
    const float4 b = ((const float4*)(g_eo + ((size_t)e1 * CAP + p1) * DM))[threadIdx.x];
    float4 o;
    o.x = w0 * a.x + w1 * b.x;
    o.y = w0 * a.y + w1 * b.y;
    o.z = w0 * a.z + w1 * b.z;
    o.w = w0 * a.w + w1 * b.w;
    ((float4*)(out + (size_t)n * DM))[threadIdx.x] = o;
}

// ---------------------------------------------------------------------------
extern "C" void kernel_launch(void* const* d_in, const int* in_sizes, int n_in,
                              void* d_out, int out_size) {
    const float *x = nullptr, *wg = nullptr, *cfc = nullptr, *cpr = nullptr;
    for (int i = 0; i < n_in; i++) {
        switch (in_sizes[i]) {
            case 16777216: x   = (const float*)d_in[i]; break;  // [8,2048,1024]
            case 8192:     wg  = (const float*)d_in[i]; break;  // [1024,8]
            case 25165824: cfc = (const float*)d_in[i]; break;  // [8,1024,3072]
            case 12582912: cpr = (const float*)d_in[i]; break;  // [8,1536,1024]
        }
    }
    float* out = (float*)d_out;

    cudaFuncSetAttribute(gemm_mma, cudaFuncAttributeMaxDynamicSharedMemorySize, GEMM_SMEM);

    gate_kernel  <<<N_TOK / 4, 128>>>(x, wg);
    count_kernel <<<NBLK, 1024>>>();
    scan_kernel  <<<1, NE>>>();
    pos_kernel   <<<NBLK, 1024>>>();
    scatter_fp16 <<<NSLOT, 256>>>(x);

    wsplit_kernel<<<dim3(DFF / 32, DM / 32, NE), dim3(32, 8)>>>(cfc, 0, DM, DFF);  // W1 (interleaved)
    wsplit_kernel<<<dim3(DM / 32, DH / 32, NE), dim3(32, 8)>>>(cpr, 1, DH, DM);    // W2

    gemm_mma<<<dim3(DFF / TN, CAP / TM, NE), 256, GEMM_SMEM>>>(0, DFF, DM);   // fused H+SwiGLU -> g_hg
    gemm_mma<<<dim3(DM / TN, CAP / TM, NE), 256, GEMM_SMEM>>>(1, DM, DH);     // O = HG @ W2^T -> g_eo

    combine_kernel<<<N_TOK, 256>>>(out);
}

// round 9
// speedup vs baseline: 4.6105x; 1.0139x over previous
#include <cuda_runtime.h>
#include <cuda_fp16.h>
#include <stdint.h>
#include <math.h>

// ---------------------------------------------------------------------------
// MoE: gate -> top2 route -> capacity dispatch -> 8x SwiGLU expert MLP -> combine
// Expert GEMMs: mma.sync fp16 (fp32 acc), persistent CTAs + cross-tile cp.async
// pipeline. GEMM1 epilogue = fused SwiGLU via interleaved W1^T, smem-staged
// coalesced fp16 stores.
// ---------------------------------------------------------------------------

#define N_TOK   16384
#define DM      1024
#define NE      8
#define CAP     4096
#define DFF     3072
#define DH      1536
#define NSLOT   (N_TOK * 2)
#define NBLK    32

// GEMM tiling
#define TM      128
#define TN      256
#define TK      32
#define STAGE_B 30720                 // A: 128*80  +  B: 256*80
#define EP_OFF  (3 * STAGE_B)         // epilogue staging buffer (gemm1)
#define GEMM_SMEM (EP_OFF + 128 * 136 * 2)   // 126976

// ---- scratch (device globals: allocation-free rule) ----
__device__ float  g_eo[(size_t)NE * CAP * DM];     // expert output (fp32)
__device__ __half g_ax[(size_t)NE * CAP * DM];     // dispatched x (fp16)
__device__ __half g_hg[(size_t)NE * CAP * DH];     // swiglu out (fp16)
__device__ __half g_w1[(size_t)NE * DFF * DM];     // W1^T interleaved [E][3072][1024]
__device__ __half g_w2[(size_t)NE * DM * DH];      // W2^T [E][1024][1536]
__device__ int   g_se[NSLOT];
__device__ float g_sw[NSLOT];
__device__ int   g_sp[NSLOT];
__device__ int   g_bcnt[NBLK * NE];
__device__ int   g_boff[NBLK * NE];

// ---------------------------------------------------------------------------
// helpers
// ---------------------------------------------------------------------------
__device__ __forceinline__ uint32_t smem_u32(const void* p) {
    uint32_t a;
    asm("{ .reg .u64 t; cvta.to.shared.u64 t, %1; cvt.u32.u64 %0, t; }"
        : "=r"(a) : "l"(p));
    return a;
}
__device__ __forceinline__ void cp16(uint32_t dst, const void* src) {
    asm volatile("cp.async.cg.shared.global [%0], [%1], 16;" :: "r"(dst), "l"(src));
}
#define CP_COMMIT() asm volatile("cp.async.commit_group;" ::: "memory")

#define LDSM4(v, addr) \
    asm volatile("ldmatrix.sync.aligned.m8n8.x4.shared.b16 {%0,%1,%2,%3}, [%4];" \
        : "=r"((v)[0]), "=r"((v)[1]), "=r"((v)[2]), "=r"((v)[3]) : "r"(addr))

#define MMA16816(c, a, b0, b1) \
    asm volatile("mma.sync.aligned.m16n8k16.row.col.f32.f16.f16.f32 " \
        "{%0,%1,%2,%3}, {%4,%5,%6,%7}, {%8,%9}, {%0,%1,%2,%3};" \
        : "+f"((c)[0]), "+f"((c)[1]), "+f"((c)[2]), "+f"((c)[3]) \
        : "r"((a)[0]), "r"((a)[1]), "r"((a)[2]), "r"((a)[3]), "r"(b0), "r"(b1))

// ---------------------------------------------------------------------------
// Gate: logits -> softmax -> top2 (ties: lowest index)
// ---------------------------------------------------------------------------
__global__ void gate_kernel(const float* __restrict__ x, const float* __restrict__ wg) {
    __shared__ float wgs[NE][DM];
    const int tid = threadIdx.x;
    for (int i = tid; i < NE * DM; i += blockDim.x)
        wgs[i & 7][i >> 3] = wg[i];
    __syncthreads();

    const int warp = tid >> 5, lane = tid & 31;
    const int n = blockIdx.x * 4 + warp;

    float acc[NE];
    #pragma unroll
    for (int e = 0; e < NE; e++) acc[e] = 0.f;
    const float* xr = x + (size_t)n * DM;
    for (int j = lane; j < DM; j += 32) {
        const float xv = xr[j];
        #pragma unroll
        for (int e = 0; e < NE; e++) acc[e] += xv * wgs[e][j];
    }
    #pragma unroll
    for (int off = 16; off; off >>= 1)
        #pragma unroll
        for (int e = 0; e < NE; e++)
            acc[e] += __shfl_xor_sync(0xffffffffu, acc[e], off);

    if (lane == 0) {
        float m = acc[0];
        #pragma unroll
        for (int e = 1; e < NE; e++) m = fmaxf(m, acc[e]);
        float p[NE], s = 0.f;
        #pragma unroll
        for (int e = 0; e < NE; e++) { p[e] = expf(acc[e] - m); s += p[e]; }
        const float inv = 1.f / s;
        #pragma unroll
        for (int e = 0; e < NE; e++) p[e] *= inv;
        int e1 = 0;
        #pragma unroll
        for (int e = 1; e < NE; e++) if (p[e] > p[e1]) e1 = e;
        int e2 = (e1 == 0) ? 1 : 0;
        #pragma unroll
        for (int e = 0; e < NE; e++) if (e != e1 && p[e] > p[e2]) e2 = e;
        g_se[2*n]   = e1;  g_sw[2*n]   = p[e1];
        g_se[2*n+1] = e2;  g_sw[2*n+1] = p[e2];
    }
}

// ---------------------------------------------------------------------------
// Rank: per-expert exclusive position over slots in flat order
// ---------------------------------------------------------------------------
__global__ void count_kernel() {
    __shared__ int c[NE];
    if (threadIdx.x < NE) c[threadIdx.x] = 0;
    __syncthreads();
    atomicAdd(&c[g_se[blockIdx.x * 1024 + threadIdx.x]], 1);
    __syncthreads();
    if (threadIdx.x < NE) g_bcnt[blockIdx.x * NE + threadIdx.x] = c[threadIdx.x];
}
__global__ void scan_kernel() {
    const int e = threadIdx.x;
    int run = 0;
    for (int b = 0; b < NBLK; b++) { g_boff[b * NE + e] = run; run += g_bcnt[b * NE + e]; }
}
__global__ void pos_kernel() {
    __shared__ int el[1024];
    const int t = threadIdx.x;
    const int s = blockIdx.x * 1024 + t;
    const int e = g_se[s];
    el[t] = e;
    __syncthreads();
    int r = g_boff[blockIdx.x * NE + e];
    for (int j = 0; j < t; j++) r += (el[j] == e);
    g_sp[s] = (r < CAP) ? r : -1;
}

// ---------------------------------------------------------------------------
// Scatter: x rows -> fp16 into exp slot
// ---------------------------------------------------------------------------
__global__ void scatter_fp16(const float* __restrict__ x) {
    const int s = blockIdx.x;
    const int p = g_sp[s];
    if (p < 0) return;
    const int e = g_se[s];
    const int tok = s >> 1;
    const float4 v = ((const float4*)(x + (size_t)tok * DM))[threadIdx.x];
    __half h[4] = { __float2half(v.x), __float2half(v.y),
                    __float2half(v.z), __float2half(v.w) };
    *(uint2*)&g_ax[((size_t)e * CAP + p) * DM + threadIdx.x * 4] = *(uint2*)h;
}

// ---------------------------------------------------------------------------
// Weight transpose -> fp16. which==0 (W1): interleave dest rows so that
//   dest row 2j   = fc column j         (a / silu input)
//   dest row 2j+1 = fc column j + 1536  (g / gate input)
// which==1 (W2): plain transpose.
// ---------------------------------------------------------------------------
__global__ void wsplit_kernel(const float* __restrict__ W, const int which,
                              const int K, const int N) {
    __shared__ float s[32][33];
    __half* D = which ? g_w2 : g_w1;
    const int e = blockIdx.z;
    const int n0 = blockIdx.x * 32, k0 = blockIdx.y * 32;
    const float* src = W + (size_t)e * K * N;
    const int tx = threadIdx.x, ty = threadIdx.y;   // 32 x 8

    int scol;
    if (which == 0) scol = (tx < 16) ? (n0 / 2 + tx) : (n0 / 2 + DH + (tx - 16));
    else            scol = n0 + tx;

    #pragma unroll
    for (int i = 0; i < 4; i++)
        s[ty + i*8][tx] = src[(size_t)(k0 + ty + i*8) * N + scol];
    __syncthreads();

    const size_t dbase = (size_t)e * N * K;
    #pragma unroll
    for (int i = 0; i < 4; i++) {
        const int r = ty + i*8;
        const int c = which == 0 ? ((r & 1) ? 16 + (r >> 1) : (r >> 1)) : r;
        D[dbase + (size_t)(n0 + r) * K + k0 + tx] = __float2half(s[tx][c]);
    }
}

// ---------------------------------------------------------------------------
// Persistent batched GEMM: C[e][M][N] = A[e][M][K] @ B[e][N][K]^T (fp16, f32 acc)
// Grid = numSM CTAs; each walks tiles bid, bid+NC, ... with a continuous
// 3-slot cp.async ring spanning tile boundaries (no refill bubble).
// which==0: epilogue = fused SwiGLU, smem-staged, fp16 -> g_hg.
// which==1: direct fp32 stores -> g_eo.
// ---------------------------------------------------------------------------
__device__ __forceinline__ void load_stage(
    uint32_t sdst,
    const __half* __restrict__ A, const __half* __restrict__ B,
    const int K, const int k0, const int tid)
{
    #pragma unroll
    for (int i = 0; i < 6; i++) {
        const int L = i * 256 + tid;          // 0..1535
        const int rid = L >> 2, q = L & 3;
        const __half* src;
        uint32_t dst;
        if (rid < 128) { src = A + (size_t)rid * K;                 dst = sdst +         rid * 80; }
        else           { const int r = rid - 128; src = B + (size_t)r * K; dst = sdst + 10240 + r * 80; }
        cp16(dst + q * 16, src + k0 + q * 8);
    }
}

__global__ void __launch_bounds__(256, 1)
gemm_mma(const int which, const int N, const int K)
{
    extern __shared__ char smem[];
    const uint32_t sb = smem_u32(smem);
    const int tid = threadIdx.x, wid = tid >> 5, lane = tid & 31;
    const int wm = wid & 1, wn = wid >> 1;          // 2 x 4 warp grid, warp 64x64
    const int gq = lane >> 2, tg = lane & 3;

    const __half *gA, *gB;
    if (which == 0) { gA = g_ax; gB = g_w1; }
    else            { gA = g_hg; gB = g_w2; }

    const int nbx = N / TN;
    const int per_e = nbx * (CAP / TM);
    const int NT = per_e * NE;
    const int NC = gridDim.x;
    const int myNT = (NT - (int)blockIdx.x + NC - 1) / NC;
    if (myNT <= 0) return;
    const int T = K / TK;
    const int G = myNT * T;

    // ---- loader state (next load = global iter l) ----
    int l_t, l_tc = 0, l_tile = blockIdx.x;
    const __half *lA, *lB;
    {
        const int e = l_tile / per_e, r = l_tile % per_e;
        lA = gA + ((size_t)e * CAP + (r / nbx) * TM) * K;
        lB = gB + ((size_t)e * N + (r % nbx) * TN) * K;
    }
    load_stage(sb,           lA, lB, K, 0,  tid);  CP_COMMIT();
    load_stage(sb + STAGE_B, lA, lB, K, TK, tid);  CP_COMMIT();
    l_t = 2;   // T >= 32, so both prologue loads belong to the first tile

    const int lmr = lane & 15;
    const int lmk = (lane >> 4) << 3;

    int g = 0;
    int c_tile = blockIdx.x;
    for (int tc = 0; tc < myNT; tc++, c_tile += NC) {
        float acc[128];
        #pragma unroll
        for (int i = 0; i < 128; i++) acc[i] = 0.f;

        for (int t = 0; t < T; t++, g++) {
            if (g + 1 < G) asm volatile("cp.async.wait_group 1;" ::: "memory");
            else           asm volatile("cp.async.wait_group 0;" ::: "memory");
            __syncthreads();   // stage g visible to all; slot (g-1) compute retired

            if (g + 2 < G) {   // continuous ring: may cross into the next tile
                load_stage(sb + ((g + 2) % 3) * STAGE_B, lA, lB, K, l_t * TK, tid);
                CP_COMMIT();
                if (++l_t == T) {
                    l_t = 0; l_tc++; l_tile += NC;
                    if (l_tc < myNT) {
                        const int e = l_tile / per_e, r = l_tile % per_e;
                        lA = gA + ((size_t)e * CAP + (r / nbx) * TM) * K;
                        lB = gB + ((size_t)e * N + (r % nbx) * TN) * K;
                    }
                }
            }

            const uint32_t sst = sb + (g % 3) * STAGE_B;
            #pragma unroll
            for (int kk = 0; kk < 2; kk++) {
                const uint32_t koff = (kk * 16 + lmk) * 2;
                const uint32_t aA = sst + (wm * 64 + lmr) * 80 + koff;
                const uint32_t aB = sst + 10240 + (wn * 64 + lmr) * 80 + koff;

                uint32_t ah[16], bh[16], q[4];
                LDSM4(&ah[0],  aA);
                LDSM4(&ah[4],  aA + 1280);
                LDSM4(&ah[8],  aA + 2560);
                LDSM4(&ah[12], aA + 3840);
                #pragma unroll
                for (int u = 0; u < 4; u++) {
                    LDSM4(q, aB + u * 1280);
                    bh[4*u+0] = q[0]; bh[4*u+1] = q[2]; bh[4*u+2] = q[1]; bh[4*u+3] = q[3];
                }
                #pragma unroll
                for (int i = 0; i < 4; i++)
                    #pragma unroll
                    for (int j = 0; j < 8; j++)
                        MMA16816(&acc[(i*8+j)*4], &ah[i*4], bh[2*j], bh[2*j+1]);
            }
        }

        // ---- epilogue for c_tile ----
        const int e = c_tile / per_e, r = c_tile % per_e;
        const int bm = (r / nbx) * TM, bn = (r % nbx) * TN;

        if (which == 0) {
            // Fused SwiGLU -> smem stage [128][136] halves -> coalesced stores
            __half* EP = (__half*)(smem + EP_OFF);
            #pragma unroll
            for (int i = 0; i < 4; i++) {
                const int lr = wm * 64 + i * 16 + gq;
                #pragma unroll
                for (int j = 0; j < 8; j++) {
                    const int lc = wn * 32 + j * 4 + tg;
                    const float* c = &acc[(i*8+j)*4];
                    const float h0 = (c[0] / (1.f + expf(-c[0]))) * c[1];
                    const float h1 = (c[2] / (1.f + expf(-c[2]))) * c[3];
                    EP[lr * 136 + lc]       = __float2half(h0);
                    EP[(lr + 8) * 136 + lc] = __float2half(h1);
                }
            }
            __syncthreads();
            __half* HG = g_hg + (size_t)e * CAP * DH + (bn >> 1);
            #pragma unroll
            for (int it = 0; it < 8; it++) {
                const int idx = it * 256 + tid;       // 128 rows x 16 uint4
                const int rr = idx >> 4, qq = idx & 15;
                *(uint4*)&HG[(size_t)(bm + rr) * DH + qq * 8] =
                    *(uint4*)&EP[rr * 136 + qq * 8];
            }
        } else {
            float* C = g_eo + (size_t)e * CAP * N;
            #pragma unroll
            for (int i = 0; i < 4; i++) {
                const int row = bm + wm * 64 + i * 16 + gq;
                #pragma unroll
                for (int j = 0; j < 8; j++) {
                    const int col = bn + wn * 64 + j * 8 + tg * 2;
                    float* p = C + (size_t)row * N + col;
                    const float* c = &acc[(i*8+j)*4];
                    *(float2*)p           = make_float2(c[0], c[1]);
                    *(float2*)(p + 8 * N) = make_float2(c[2], c[3]);
                }
            }
        }
    }
}

// ---------------------------------------------------------------------------
// Combine: out[n] = w0*eo[e0,p0] + w1*eo[e1,p1]
// ---------------------------------------------------------------------------
__global__ void combine_kernel(float* __restrict__ out) {
    const int n = blockIdx.x;
    const int s0 = 2 * n;
    float w0 = g_sw[s0], w1 = g_sw[s0 + 1];
    int   p0 = g_sp[s0], p1 = g_sp[s0 + 1];
    const int e0 = g_se[s0], e1 = g_se[s0 + 1];
    if (p0 < 0) { w0 = 0.f; p0 = 0; }
    if (p1 < 0) { w1 = 0.f; p1 = 0; }
    const float4 a = ((const float4*)(g_eo + ((size_t)e0 * CAP + p0) * DM))[threadIdx.x];
    const float4 b = ((const float4*)(g_eo + ((size_t)e1 * CAP + p1) * DM))[threadIdx.x];
    float4 o;
    o.x = w0 * a.x + w1 * b.x;
    o.y = w0 * a.y + w1 * b.y;
    o.z = w0 * a.z + w1 * b.z;
    o.w = w0 * a.w + w1 * b.w;
    ((float4*)(out + (size_t)n * DM))[threadIdx.x] = o;
}

// ---------------------------------------------------------------------------
extern "C" void kernel_launch(void* const* d_in, const int* in_sizes, int n_in,
                              void* d_out, int out_size) {
    const float *x = nullptr, *wg = nullptr, *cfc = nullptr, *cpr = nullptr;
    for (int i = 0; i < n_in; i++) {
        switch (in_sizes[i]) {
            case 16777216: x   = (const float*)d_in[i]; break;  // [8,2048,1024]
            case 8192:     wg  = (const float*)d_in[i]; break;  // [1024,8]
            case 25165824: cfc = (const float*)d_in[i]; break;  // [8,1024,3072]
            case 12582912: cpr = (const float*)d_in[i]; break;  // [8,1536,1024]
        }
    }
    float* out = (float*)d_out;

    int nsm = 148;
    cudaDeviceGetAttribute(&nsm, cudaDevAttrMultiProcessorCount, 0);
    cudaFuncSetAttribute(gemm_mma, cudaFuncAttributeMaxDynamicSharedMemorySize, GEMM_SMEM);

    gate_kernel  <<<N_TOK / 4, 128>>>(x, wg);
    count_kernel <<<NBLK, 1024>>>();
    scan_kernel  <<<1, NE>>>();
    pos_kernel   <<<NBLK, 1024>>>();
    scatter_fp16 <<<NSLOT, 256>>>(x);

    wsplit_kernel<<<dim3(DFF / 32, DM / 32, NE), dim3(32, 8)>>>(cfc, 0, DM, DFF);  // W1 (interleaved)
    wsplit_kernel<<<dim3(DM / 32, DH / 32, NE), dim3(32, 8)>>>(cpr, 1, DH, DM);    // W2

    gemm_mma<<<nsm, 256, GEMM_SMEM>>>(0, DFF, DM);   // fused H+SwiGLU -> g_hg
    gemm_mma<<<nsm, 256, GEMM_SMEM>>>(1, DM, DH);    // O = HG @ W2^T -> g_eo

    combine_kernel<<<N_TOK, 256>>>(out);
}

// round 10
// speedup vs baseline: 5.2146x; 1.1310x over previous
#include <cuda_runtime.h>
#include <cuda_fp16.h>
#include <stdint.h>
#include <math.h>

// ---------------------------------------------------------------------------
// MoE: gate -> top2 route -> capacity dispatch -> 8x SwiGLU expert MLP -> combine
// Expert GEMMs: mma.sync fp16 (fp32 acc), persistent CTAs, TK=64 K-tiles
// (halved per-iteration sync/LDSM overhead), continuous 3-slot cp.async ring.
// GEMM1 epilogue = fused SwiGLU via interleaved W1^T, smem-staged stores.
// ---------------------------------------------------------------------------

#define N_TOK   16384
#define DM      1024
#define NE      8
#define CAP     4096
#define DFF     3072
#define DH      1536
#define NSLOT   (N_TOK * 2)
#define NBLK    32

// GEMM tiling
#define TM      128
#define TN      256
#define TK      64
#define ROWB    160                   // 128B data + 32B pad (conflict-free ldmatrix)
#define STAGE_B 61440                 // A: 128*160  +  B: 256*160
#define EP_OFF  (3 * STAGE_B)         // epilogue staging buffer (gemm1)
#define GEMM_SMEM (EP_OFF + 128 * 136 * 2)   // 219136

// ---- scratch (device globals: allocation-free rule) ----
__device__ float  g_eo[(size_t)NE * CAP * DM];     // expert output (fp32)
__device__ __half g_ax[(size_t)NE * CAP * DM];     // dispatched x (fp16)
__device__ __half g_hg[(size_t)NE * CAP * DH];     // swiglu out (fp16)
__device__ __half g_w1[(size_t)NE * DFF * DM];     // W1^T interleaved [E][3072][1024]
__device__ __half g_w2[(size_t)NE * DM * DH];      // W2^T [E][1024][1536]
__device__ int   g_se[NSLOT];
__device__ float g_sw[NSLOT];
__device__ int   g_sp[NSLOT];
__device__ int   g_bcnt[NBLK * NE];
__device__ int   g_boff[NBLK * NE];

// ---------------------------------------------------------------------------
// helpers
// ---------------------------------------------------------------------------
__device__ __forceinline__ uint32_t smem_u32(const void* p) {
    uint32_t a;
    asm("{ .reg .u64 t; cvta.to.shared.u64 t, %1; cvt.u32.u64 %0, t; }"
        : "=r"(a) : "l"(p));
    return a;
}
__device__ __forceinline__ void cp16(uint32_t dst, const void* src) {
    asm volatile("cp.async.cg.shared.global [%0], [%1], 16;" :: "r"(dst), "l"(src));
}
#define CP_COMMIT() asm volatile("cp.async.commit_group;" ::: "memory")

#define LDSM4(v, addr) \
    asm volatile("ldmatrix.sync.aligned.m8n8.x4.shared.b16 {%0,%1,%2,%3}, [%4];" \
        : "=r"((v)[0]), "=r"((v)[1]), "=r"((v)[2]), "=r"((v)[3]) : "r"(addr))

#define MMA16816(c, a, b0, b1) \
    asm volatile("mma.sync.aligned.m16n8k16.row.col.f32.f16.f16.f32 " \
        "{%0,%1,%2,%3}, {%4,%5,%6,%7}, {%8,%9}, {%0,%1,%2,%3};" \
        : "+f"((c)[0]), "+f"((c)[1]), "+f"((c)[2]), "+f"((c)[3]) \
        : "r"((a)[0]), "r"((a)[1]), "r"((a)[2]), "r"((a)[3]), "r"(b0), "r"(b1))

// ---------------------------------------------------------------------------
// Gate: logits -> softmax -> top2 (ties: lowest index)
// ---------------------------------------------------------------------------
__global__ void gate_kernel(const float* __restrict__ x, const float* __restrict__ wg) {
    __shared__ float wgs[NE][DM];
    const int tid = threadIdx.x;
    for (int i = tid; i < NE * DM; i += blockDim.x)
        wgs[i & 7][i >> 3] = wg[i];
    __syncthreads();

    const int warp = tid >> 5, lane = tid & 31;
    const int n = blockIdx.x * 4 + warp;

    float acc[NE];
    #pragma unroll
    for (int e = 0; e < NE; e++) acc[e] = 0.f;
    const float* xr = x + (size_t)n * DM;
    for (int j = lane; j < DM; j += 32) {
        const float xv = xr[j];
        #pragma unroll
        for (int e = 0; e < NE; e++) acc[e] += xv * wgs[e][j];
    }
    #pragma unroll
    for (int off = 16; off; off >>= 1)
        #pragma unroll
        for (int e = 0; e < NE; e++)
            acc[e] += __shfl_xor_sync(0xffffffffu, acc[e], off);

    if (lane == 0) {
        float m = acc[0];
        #pragma unroll
        for (int e = 1; e < NE; e++) m = fmaxf(m, acc[e]);
        float p[NE], s = 0.f;
        #pragma unroll
        for (int e = 0; e < NE; e++) { p[e] = expf(acc[e] - m); s += p[e]; }
        const float inv = 1.f / s;
        #pragma unroll
        for (int e = 0; e < NE; e++) p[e] *= inv;
        int e1 = 0;
        #pragma unroll
        for (int e = 1; e < NE; e++) if (p[e] > p[e1]) e1 = e;
        int e2 = (e1 == 0) ? 1 : 0;
        #pragma unroll
        for (int e = 0; e < NE; e++) if (e != e1 && p[e] > p[e2]) e2 = e;
        g_se[2*n]   = e1;  g_sw[2*n]   = p[e1];
        g_se[2*n+1] = e2;  g_sw[2*n+1] = p[e2];
    }
}

// ---------------------------------------------------------------------------
// Rank: per-expert exclusive position over slots in flat order
// ---------------------------------------------------------------------------
__global__ void count_kernel() {
    __shared__ int c[NE];
    if (threadIdx.x < NE) c[threadIdx.x] = 0;
    __syncthreads();
    atomicAdd(&c[g_se[blockIdx.x * 1024 + threadIdx.x]], 1);
    __syncthreads();
    if (threadIdx.x < NE) g_bcnt[blockIdx.x * NE + threadIdx.x] = c[threadIdx.x];
}
__global__ void scan_kernel() {
    const int e = threadIdx.x;
    int run = 0;
    for (int b = 0; b < NBLK; b++) { g_boff[b * NE + e] = run; run += g_bcnt[b * NE + e]; }
}
__global__ void pos_kernel() {
    __shared__ int el[1024];
    const int t = threadIdx.x;
    const int s = blockIdx.x * 1024 + t;
    const int e = g_se[s];
    el[t] = e;
    __syncthreads();
    int r = g_boff[blockIdx.x * NE + e];
    for (int j = 0; j < t; j++) r += (el[j] == e);
    g_sp[s] = (r < CAP) ? r : -1;
}

// ---------------------------------------------------------------------------
// Scatter: x rows -> fp16 into exp slot
// ---------------------------------------------------------------------------
__global__ void scatter_fp16(const float* __restrict__ x) {
    const int s = blockIdx.x;
    const int p = g_sp[s];
    if (p < 0) return;
    const int e = g_se[s];
    const int tok = s >> 1;
    const float4 v = ((const float4*)(x + (size_t)tok * DM))[threadIdx.x];
    __half h[4] = { __float2half(v.x), __float2half(v.y),
                    __float2half(v.z), __float2half(v.w) };
    *(uint2*)&g_ax[((size_t)e * CAP + p) * DM + threadIdx.x * 4] = *(uint2*)h;
}

// ---------------------------------------------------------------------------
// Weight transpose -> fp16. which==0 (W1): interleave dest rows so that
//   dest row 2j   = fc column j         (a / silu input)
//   dest row 2j+1 = fc column j + 1536  (g / gate input)
// which==1 (W2): plain transpose.
// ---------------------------------------------------------------------------
__global__ void wsplit_kernel(const float* __restrict__ W, const int which,
                              const int K, const int N) {
    __shared__ float s[32][33];
    __half* D = which ? g_w2 : g_w1;
    const int e = blockIdx.z;
    const int n0 = blockIdx.x * 32, k0 = blockIdx.y * 32;
    const float* src = W + (size_t)e * K * N;
    const int tx = threadIdx.x, ty = threadIdx.y;   // 32 x 8

    int scol;
    if (which == 0) scol = (tx < 16) ? (n0 / 2 + tx) : (n0 / 2 + DH + (tx - 16));
    else            scol = n0 + tx;

    #pragma unroll
    for (int i = 0; i < 4; i++)
        s[ty + i*8][tx] = src[(size_t)(k0 + ty + i*8) * N + scol];
    __syncthreads();

    const size_t dbase = (size_t)e * N * K;
    #pragma unroll
    for (int i = 0; i < 4; i++) {
        const int r = ty + i*8;
        const int c = which == 0 ? ((r & 1) ? 16 + (r >> 1) : (r >> 1)) : r;
        D[dbase + (size_t)(n0 + r) * K + k0 + tx] = __float2half(s[tx][c]);
    }
}

// ---------------------------------------------------------------------------
// Persistent batched GEMM: C[e][M][N] = A[e][M][K] @ B[e][N][K]^T (fp16, f32 acc)
// Grid = numSM CTAs, continuous 3-slot cp.async ring, TK=64 K-tiles.
// which==0: epilogue = fused SwiGLU, smem-staged, fp16 -> g_hg.
// which==1: direct fp32 stores -> g_eo.
// ---------------------------------------------------------------------------
__device__ __forceinline__ void load_stage(
    uint32_t sdst,
    const __half* __restrict__ A, const __half* __restrict__ B,
    const int K, const int k0, const int tid)
{
    // 384 rows (A:128, B:256), 8 x 16B quads per row; 12 cp16/thread
    #pragma unroll
    for (int i = 0; i < 12; i++) {
        const int L = i * 256 + tid;          // 0..3071
        const int rid = L >> 3, q = L & 7;
        const __half* src;
        uint32_t dst;
        if (rid < 128) { src = A + (size_t)rid * K;                 dst = sdst +         rid * ROWB; }
        else           { const int r = rid - 128; src = B + (size_t)r * K; dst = sdst + 20480 + r * ROWB; }
        cp16(dst + q * 16, src + k0 + q * 8);
    }
}

__global__ void __launch_bounds__(256, 1)
gemm_mma(const int which, const int N, const int K)
{
    extern __shared__ char smem[];
    const uint32_t sb = smem_u32(smem);
    const int tid = threadIdx.x, wid = tid >> 5, lane = tid & 31;
    const int wm = wid & 1, wn = wid >> 1;          // 2 x 4 warp grid, warp 64x64
    const int gq = lane >> 2, tg = lane & 3;

    const __half *gA, *gB;
    if (which == 0) { gA = g_ax; gB = g_w1; }
    else            { gA = g_hg; gB = g_w2; }

    const int nbx = N / TN;
    const int per_e = nbx * (CAP / TM);
    const int NT = per_e * NE;
    const int NC = gridDim.x;
    const int myNT = (NT - (int)blockIdx.x + NC - 1) / NC;
    if (myNT <= 0) return;
    const int T = K / TK;                 // 16 (gemm1) / 24 (gemm2)
    const int G = myNT * T;

    // ---- loader state (next load = global iter l) ----
    int l_t, l_tc = 0, l_tile = blockIdx.x;
    const __half *lA, *lB;
    {
        const int e = l_tile / per_e, r = l_tile % per_e;
        lA = gA + ((size_t)e * CAP + (r / nbx) * TM) * K;
        lB = gB + ((size_t)e * N + (r % nbx) * TN) * K;
    }
    load_stage(sb,           lA, lB, K, 0,  tid);  CP_COMMIT();
    load_stage(sb + STAGE_B, lA, lB, K, TK, tid);  CP_COMMIT();
    l_t = 2;   // T >= 16, so both prologue loads belong to the first tile

    const int lmr = lane & 15;
    const int lmk = (lane >> 4) << 3;

    int g = 0;
    int c_tile = blockIdx.x;
    for (int tc = 0; tc < myNT; tc++, c_tile += NC) {
        float acc[128];
        #pragma unroll
        for (int i = 0; i < 128; i++) acc[i] = 0.f;

        for (int t = 0; t < T; t++, g++) {
            if (g + 1 < G) asm volatile("cp.async.wait_group 1;" ::: "memory");
            else           asm volatile("cp.async.wait_group 0;" ::: "memory");
            __syncthreads();   // stage g visible to all; slot (g-1) compute retired

            if (g + 2 < G) {   // continuous ring: may cross into the next tile
                load_stage(sb + ((g + 2) % 3) * STAGE_B, lA, lB, K, l_t * TK, tid);
                CP_COMMIT();
                if (++l_t == T) {
                    l_t = 0; l_tc++; l_tile += NC;
                    if (l_tc < myNT) {
                        const int e = l_tile / per_e, r = l_tile % per_e;
                        lA = gA + ((size_t)e * CAP + (r / nbx) * TM) * K;
                        lB = gB + ((size_t)e * N + (r % nbx) * TN) * K;
                    }
                }
            }

            const uint32_t sst = sb + (g % 3) * STAGE_B;
            #pragma unroll
            for (int kk = 0; kk < 4; kk++) {
                const uint32_t koff = (kk * 16 + lmk) * 2;
                const uint32_t aA = sst + (wm * 64 + lmr) * ROWB + koff;
                const uint32_t aB = sst + 20480 + (wn * 64 + lmr) * ROWB + koff;

                uint32_t ah[16], bh[16], q[4];
                LDSM4(&ah[0],  aA);
                LDSM4(&ah[4],  aA + 16 * ROWB);
                LDSM4(&ah[8],  aA + 32 * ROWB);
                LDSM4(&ah[12], aA + 48 * ROWB);
                #pragma unroll
                for (int u = 0; u < 4; u++) {
                    LDSM4(q, aB + u * 16 * ROWB);
                    bh[4*u+0] = q[0]; bh[4*u+1] = q[2]; bh[4*u+2] = q[1]; bh[4*u+3] = q[3];
                }
                #pragma unroll
                for (int i = 0; i < 4; i++)
                    #pragma unroll
                    for (int j = 0; j < 8; j++)
                        MMA16816(&acc[(i*8+j)*4], &ah[i*4], bh[2*j], bh[2*j+1]);
            }
        }

        // ---- epilogue for c_tile ----
        const int e = c_tile / per_e, r = c_tile % per_e;
        const int bm = (r / nbx) * TM, bn = (r % nbx) * TN;

        if (which == 0) {
            // Fused SwiGLU -> smem stage [128][136] halves -> coalesced stores
            __half* EP = (__half*)(smem + EP_OFF);
            #pragma unroll
            for (int i = 0; i < 4; i++) {
                const int lr = wm * 64 + i * 16 + gq;
                #pragma unroll
                for (int j = 0; j < 8; j++) {
                    const int lc = wn * 32 + j * 4 + tg;
                    const float* c = &acc[(i*8+j)*4];
                    const float h0 = (c[0] / (1.f + expf(-c[0]))) * c[1];
                    const float h1 = (c[2] / (1.f + expf(-c[2]))) * c[3];
                    EP[lr * 136 + lc]       = __float2half(h0);
                    EP[(lr + 8) * 136 + lc] = __float2half(h1);
                }
            }
            __syncthreads();
            __half* HG = g_hg + (size_t)e * CAP * DH + (bn >> 1);
            #pragma unroll
            for (int it = 0; it < 8; it++) {
                const int idx = it * 256 + tid;       // 128 rows x 16 uint4
                const int rr = idx >> 4, qq = idx & 15;
                *(uint4*)&HG[(size_t)(bm + rr) * DH + qq * 8] =
                    *(uint4*)&EP[rr * 136 + qq * 8];
            }
        } else {
            float* C = g_eo + (size_t)e * CAP * N;
            #pragma unroll
            for (int i = 0; i < 4; i++) {
                const int row = bm + wm * 64 + i * 16 + gq;
                #pragma unroll
                for (int j = 0; j < 8; j++) {
                    const int col = bn + wn * 64 + j * 8 + tg * 2;
                    float* p = C + (size_t)row * N + col;
                    const float* c = &acc[(i*8+j)*4];
                    *(float2*)p           = make_float2(c[0], c[1]);
                    *(float2*)(p + 8 * N) = make_float2(c[2], c[3]);
                }
            }
        }
    }
}

// ---------------------------------------------------------------------------
// Combine: out[n] = w0*eo[e0,p0] + w1*eo[e1,p1]
// ---------------------------------------------------------------------------
__global__ void combine_kernel(float* __restrict__ out) {
    const int n = blockIdx.x;
    const int s0 = 2 * n;
    float w0 = g_sw[s0], w1 = g_sw[s0 + 1];
    int   p0 = g_sp[s0], p1 = g_sp[s0 + 1];
    const int e0 = g_se[s0], e1 = g_se[s0 + 1];
    if (p0 < 0) { w0 = 0.f; p0 = 0; }
    if (p1 < 0) { w1 = 0.f; p1 = 0; }
    const float4 a = ((const float4*)(g_eo + ((size_t)e0 * CAP + p0) * DM))[threadIdx.x];
    const float4 b = ((const float4*)(g_eo + ((size_t)e1 * CAP + p1) * DM))[threadIdx.x];
    float4 o;
    o.x = w0 * a.x + w1 * b.x;
    o.y = w0 * a.y + w1 * b.y;
    o.z = w0 * a.z + w1 * b.z;
    o.w = w0 * a.w + w1 * b.w;
    ((float4*)(out + (size_t)n * DM))[threadIdx.x] = o;
}

// ---------------------------------------------------------------------------
extern "C" void kernel_launch(void* const* d_in, const int* in_sizes, int n_in,
                              void* d_out, int out_size) {
    const float *x = nullptr, *wg = nullptr, *cfc = nullptr, *cpr = nullptr;
    for (int i = 0; i < n_in; i++) {
        switch (in_sizes[i]) {
            case 16777216: x   = (const float*)d_in[i]; break;  // [8,2048,1024]
            case 8192:     wg  = (const float*)d_in[i]; break;  // [1024,8]
            case 25165824: cfc = (const float*)d_in[i]; break;  // [8,1024,3072]
            case 12582912: cpr = (const float*)d_in[i]; break;  // [8,1536,1024]
        }
    }
    float* out = (float*)d_out;

    int nsm = 148;
    cudaDeviceGetAttribute(&nsm, cudaDevAttrMultiProcessorCount, 0);
    cudaFuncSetAttribute(gemm_mma, cudaFuncAttributeMaxDynamicSharedMemorySize, GEMM_SMEM);

    gate_kernel  <<<N_TOK / 4, 128>>>(x, wg);
    count_kernel <<<NBLK, 1024>>>();
    scan_kernel  <<<1, NE>>>();
    pos_kernel   <<<NBLK, 1024>>>();
    scatter_fp16 <<<NSLOT, 256>>>(x);

    wsplit_kernel<<<dim3(DFF / 32, DM / 32, NE), dim3(32, 8)>>>(cfc, 0, DM, DFF);  // W1 (interleaved)
    wsplit_kernel<<<dim3(DM / 32, DH / 32, NE), dim3(32, 8)>>>(cpr, 1, DH, DM);    // W2

    gemm_mma<<<nsm, 256, GEMM_SMEM>>>(0, DFF, DM);   // fused H+SwiGLU -> g_hg
    gemm_mma<<<nsm, 256, GEMM_SMEM>>>(1, DM, DH);    // O = HG @ W2^T -> g_eo

    combine_kernel<<<N_TOK, 256>>>(out);
}